// round 12
// baseline (speedup 1.0000x reference)
#include <cuda_runtime.h>
#include <cuda_bf16.h>
#include <math.h>
#include <stdint.h>

// Problem constants
#define D_MODEL 1024
#define NHEAD   16
#define D_K     64
#define B_SZ    2
#define SEQ     2048
#define M_ROWS  (B_SZ * SEQ)        // 4096

// Scratch (allocation-free rule: __device__ globals)
__device__ float g_Qh[B_SZ * NHEAD * SEQ * D_K];   // [B,H,S,64]
__device__ float g_Kh[B_SZ * NHEAD * SEQ * D_K];
__device__ float g_Vh[B_SZ * NHEAD * SEQ * D_K];
__device__ float g_At[B_SZ * SEQ * D_MODEL];       // [B,S,D] merged heads

__device__ __forceinline__ uint32_t f2tf32(float x) {
    uint32_t r;
    asm("cvt.rna.tf32.f32 %0, %1;" : "=r"(r) : "f"(x));
    return r;
}

__device__ __forceinline__ void mma_tf32(float c[4], const uint32_t a[4], const uint32_t b[2]) {
    asm volatile(
        "mma.sync.aligned.m16n8k8.row.col.f32.tf32.tf32.f32 "
        "{%0,%1,%2,%3}, {%4,%5,%6,%7}, {%8,%9}, {%0,%1,%2,%3};"
        : "+f"(c[0]), "+f"(c[1]), "+f"(c[2]), "+f"(c[3])
        : "r"(a[0]), "r"(a[1]), "r"(a[2]), "r"(a[3]),
          "r"(b[0]), "r"(b[1]));
}

// ---------------------------------------------------------------------------
// Software-pipelined TF32 GEMM:  C[M,N] = A[M,K] @ W[N,K]^T + bias[N]
// Block tile 128x128, BK=32, 256 threads = 8 warps (warp tile 64x32).
// Register prefetch of chunk ch+1 overlaps the 64 MMAs of chunk ch;
// double-buffered smem -> ONE __syncthreads per chunk.
// MODE 0: row-major [M,N].  MODE 1: head-split [B,H,S,64].
// ---------------------------------------------------------------------------
#define SM_STRIDE 36
#define GEMM_SMEM_BYTES (4 * 128 * SM_STRIDE * 4)   // 73728 B

template <int MODE>
__device__ __forceinline__
void gemm_body(const float* __restrict__ A,
               const float* __restrict__ W,
               const float* __restrict__ bias,
               float* __restrict__ C,
               int m0, int n0)
{
    extern __shared__ uint32_t gsm[];
    uint32_t* const bufA0 = gsm;
    uint32_t* const bufW0 = gsm + 128 * SM_STRIDE;
    uint32_t* const bufA1 = gsm + 2 * 128 * SM_STRIDE;
    uint32_t* const bufW1 = gsm + 3 * 128 * SM_STRIDE;

    const int tid  = threadIdx.x;
    const int warp = tid >> 5;
    const int lane = tid & 31;
    const int g    = lane >> 2;
    const int tg   = lane & 3;

    const int wm = (warp & 1) * 64;
    const int wn = (warp >> 1) * 32;

    // staging coordinates: thread covers rows (tid>>3)+32*i, cols (tid&7)*4..+3
    const int srow = tid >> 3;
    const int sc4  = (tid & 7) * 4;
    const float* Aptr = A + (size_t)(m0 + srow) * D_MODEL + sc4;
    const float* Wptr = W + (size_t)(n0 + srow) * D_MODEL + sc4;

    float c[4][4][4];
#pragma unroll
    for (int mi = 0; mi < 4; mi++)
#pragma unroll
        for (int ni = 0; ni < 4; ni++)
#pragma unroll
            for (int r = 0; r < 4; r++) c[mi][ni][r] = 0.0f;

    float4 va[4], vw[4];
    // prologue: chunk 0 loads
#pragma unroll
    for (int i = 0; i < 4; i++) {
        va[i] = *(const float4*)&Aptr[(size_t)(i * 32) * D_MODEL];
        vw[i] = *(const float4*)&Wptr[(size_t)(i * 32) * D_MODEL];
    }

    for (int ch = 0; ch < D_MODEL / 32; ch++) {
        uint32_t* const as = (ch & 1) ? bufA1 : bufA0;
        uint32_t* const ws = (ch & 1) ? bufW1 : bufW0;

        // store prefetched chunk (cvt hoisted here)
#pragma unroll
        for (int i = 0; i < 4; i++) {
            int row = srow + i * 32;
            uint4 ua = make_uint4(f2tf32(va[i].x), f2tf32(va[i].y), f2tf32(va[i].z), f2tf32(va[i].w));
            *(uint4*)&as[row * SM_STRIDE + sc4] = ua;
            uint4 uw = make_uint4(f2tf32(vw[i].x), f2tf32(vw[i].y), f2tf32(vw[i].z), f2tf32(vw[i].w));
            *(uint4*)&ws[row * SM_STRIDE + sc4] = uw;
        }
        __syncthreads();

        // issue next chunk's global loads (in flight during compute)
        if (ch + 1 < D_MODEL / 32) {
            const int k1 = (ch + 1) * 32;
#pragma unroll
            for (int i = 0; i < 4; i++) {
                va[i] = *(const float4*)&Aptr[(size_t)(i * 32) * D_MODEL + k1];
                vw[i] = *(const float4*)&Wptr[(size_t)(i * 32) * D_MODEL + k1];
            }
        }

        // compute chunk ch
#pragma unroll
        for (int kk = 0; kk < 32; kk += 8) {
            uint32_t a[4][4], b[4][2];
#pragma unroll
            for (int mi = 0; mi < 4; mi++) {
                int r = wm + mi * 16 + g;
                a[mi][0] = as[r * SM_STRIDE + kk + tg];
                a[mi][1] = as[(r + 8) * SM_STRIDE + kk + tg];
                a[mi][2] = as[r * SM_STRIDE + kk + tg + 4];
                a[mi][3] = as[(r + 8) * SM_STRIDE + kk + tg + 4];
            }
#pragma unroll
            for (int ni = 0; ni < 4; ni++) {
                int cn = wn + ni * 8 + g;
                b[ni][0] = ws[cn * SM_STRIDE + kk + tg];
                b[ni][1] = ws[cn * SM_STRIDE + kk + tg + 4];
            }
#pragma unroll
            for (int mi = 0; mi < 4; mi++)
#pragma unroll
                for (int ni = 0; ni < 4; ni++)
                    mma_tf32(c[mi][ni], a[mi], b[ni]);
        }
        // no trailing sync: next store targets the other buffer, and the next
        // sync (after that store) orders reuse of this one.
    }

    // Epilogue: add bias, store.
#pragma unroll
    for (int mi = 0; mi < 4; mi++) {
#pragma unroll
        for (int ni = 0; ni < 4; ni++) {
            int row = m0 + wm + mi * 16 + g;
            int col = n0 + wn + ni * 8 + 2 * tg;
#pragma unroll
            for (int rr = 0; rr < 2; rr++) {
                int m = row + rr * 8;
#pragma unroll
                for (int cc = 0; cc < 2; cc++) {
                    int n = col + cc;
                    float v = c[mi][ni][rr * 2 + cc] + bias[n];
                    if (MODE == 0) {
                        C[(size_t)m * D_MODEL + n] = v;
                    } else {
                        int bb = m >> 11;
                        int s  = m & 2047;
                        int h  = n >> 6;
                        int d  = n & 63;
                        C[(((size_t)(bb * NHEAD + h) * SEQ) + s) * D_K + d] = v;
                    }
                }
            }
        }
    }
}

// Batched Q/K/V projection: blockIdx.z selects which GEMM.
__global__ __launch_bounds__(256)
void gemm_proj3_kernel(const float* __restrict__ q,
                       const float* __restrict__ k,
                       const float* __restrict__ Wq, const float* __restrict__ bq,
                       const float* __restrict__ Wk, const float* __restrict__ bk,
                       const float* __restrict__ Wv, const float* __restrict__ bv,
                       float* __restrict__ Qh, float* __restrict__ Kh,
                       float* __restrict__ Vh)
{
    const int z = blockIdx.z;
    const float* A    = (z == 0) ? q  : k;
    const float* W    = (z == 0) ? Wq : (z == 1) ? Wk : Wv;
    const float* bias = (z == 0) ? bq : (z == 1) ? bk : bv;
    float*       C    = (z == 0) ? Qh : (z == 1) ? Kh : Vh;
    gemm_body<1>(A, W, bias, C, blockIdx.y * 128, blockIdx.x * 128);
}

// Output projection (row-major out).
__global__ __launch_bounds__(256)
void gemm_out_kernel(const float* __restrict__ A,
                     const float* __restrict__ W,
                     const float* __restrict__ bias,
                     float* __restrict__ C)
{
    gemm_body<0>(A, W, bias, C, blockIdx.y * 128, blockIdx.x * 128);
}

// ---------------------------------------------------------------------------
// Tensor-core flash attention (proven version, unchanged).
// Block: 128 threads (4 warps), 64 query rows. Key tiles of 64.
// ---------------------------------------------------------------------------
#define AT_STRIDE 68   // floats; bank = 4g+tg permutation -> conflict-free frags

__global__ __launch_bounds__(128)
void attn_mma_kernel(const int* __restrict__ qmask,
                     const int* __restrict__ kmask,
                     const int* __restrict__ causal_flag)
{
    extern __shared__ float sm[];
    float* Ps  = sm;                         // 64*AT_STRIDE (Q staging, then P)
    float* Ks  = Ps + 64 * AT_STRIDE;        // tf32-converted K tile [key][d]
    float* Vs  = Ks + 64 * AT_STRIDE;        // tf32-converted V tile [key][d]
    int*   km_s = (int*)(Vs + 64 * AT_STRIDE);

    const int tid  = threadIdx.x;
    const int warp = tid >> 5;
    const int lane = tid & 31;
    const int g    = lane >> 2;
    const int tg   = lane & 3;
    const int wrow = warp * 16;

    const int qt = (gridDim.x - 1) - blockIdx.x;   // longest blocks first
    const int bh = blockIdx.y;
    const int b  = bh >> 4;
    const int h  = bh & 15;
    const int q0 = qt * 64;
    const int causal = causal_flag[0];
    const size_t head_base = (size_t)bh * SEQ * D_K;

    {
        const float* qsrc = g_Qh + head_base + (size_t)q0 * D_K;
#pragma unroll
        for (int i = 0; i < 8; i++) {
            int lin = tid + i * 128;
            int r   = lin >> 4;
            int c4  = (lin & 15) * 4;
            float4 v = *(const float4*)&qsrc[r * 64 + c4];
            *(float4*)&Ps[r * AT_STRIDE + c4] = v;
        }
    }
    __syncthreads();

    uint32_t aq[8][4];
#pragma unroll
    for (int kf = 0; kf < 8; kf++) {
        int c = kf * 8;
        aq[kf][0] = f2tf32(Ps[(wrow + g)     * AT_STRIDE + c + tg]);
        aq[kf][1] = f2tf32(Ps[(wrow + g + 8) * AT_STRIDE + c + tg]);
        aq[kf][2] = f2tf32(Ps[(wrow + g)     * AT_STRIDE + c + tg + 4]);
        aq[kf][3] = f2tf32(Ps[(wrow + g + 8) * AT_STRIDE + c + tg + 4]);
    }

    float m_r[2] = { -INFINITY, -INFINITY };
    float l_r[2] = { 0.0f, 0.0f };
    float o[8][4];
#pragma unroll
    for (int nf = 0; nf < 8; nf++)
#pragma unroll
        for (int r = 0; r < 4; r++) o[nf][r] = 0.0f;

    const int ntiles = causal ? (qt + 1) : (SEQ / 64);

    for (int kt = 0; kt < ntiles; kt++) {
        const int k0 = kt * 64;
        __syncthreads();   // previous tile's MMA reads of Ks/Vs done
        {
            const float* ksrc = g_Kh + head_base + (size_t)k0 * D_K;
            const float* vsrc = g_Vh + head_base + (size_t)k0 * D_K;
#pragma unroll
            for (int i = 0; i < 8; i++) {
                int lin = tid + i * 128;
                int r   = lin >> 4;
                int c4  = (lin & 15) * 4;
                float4 kv = *(const float4*)&ksrc[r * 64 + c4];
                kv.x = __uint_as_float(f2tf32(kv.x));
                kv.y = __uint_as_float(f2tf32(kv.y));
                kv.z = __uint_as_float(f2tf32(kv.z));
                kv.w = __uint_as_float(f2tf32(kv.w));
                *(float4*)&Ks[r * AT_STRIDE + c4] = kv;
                float4 vv = *(const float4*)&vsrc[r * 64 + c4];
                vv.x = __uint_as_float(f2tf32(vv.x));
                vv.y = __uint_as_float(f2tf32(vv.y));
                vv.z = __uint_as_float(f2tf32(vv.z));
                vv.w = __uint_as_float(f2tf32(vv.w));
                *(float4*)&Vs[r * AT_STRIDE + c4] = vv;
            }
            if (tid < 64) km_s[tid] = kmask[b * SEQ + k0 + tid];
        }
        __syncthreads();

        float cs[8][4];
#pragma unroll
        for (int nf = 0; nf < 8; nf++)
#pragma unroll
            for (int r = 0; r < 4; r++) cs[nf][r] = 0.0f;

#pragma unroll
        for (int kf = 0; kf < 8; kf++) {
            uint32_t bk[8][2];
#pragma unroll
            for (int nf = 0; nf < 8; nf++) {
                bk[nf][0] = __float_as_uint(Ks[(nf * 8 + g) * AT_STRIDE + kf * 8 + tg]);
                bk[nf][1] = __float_as_uint(Ks[(nf * 8 + g) * AT_STRIDE + kf * 8 + tg + 4]);
            }
#pragma unroll
            for (int nf = 0; nf < 8; nf++)
                mma_tf32(cs[nf], aq[kf], bk[nf]);
        }

        const bool diag = (causal != 0) && (kt == qt);
        const int qgA = q0 + wrow + g;
        const int qgB = qgA + 8;
#pragma unroll
        for (int nf = 0; nf < 8; nf++) {
            int colb = nf * 8 + 2 * tg;
            int km0 = km_s[colb];
            int km1 = km_s[colb + 1];
            int kg0 = k0 + colb;
            int kg1 = kg0 + 1;
            float v0 = cs[nf][0] * 0.125f;
            float v1 = cs[nf][1] * 0.125f;
            float v2 = cs[nf][2] * 0.125f;
            float v3 = cs[nf][3] * 0.125f;
            if (km0 == 0 || (diag && kg0 > qgA)) v0 = -INFINITY;
            if (km1 == 0 || (diag && kg1 > qgA)) v1 = -INFINITY;
            if (km0 == 0 || (diag && kg0 > qgB)) v2 = -INFINITY;
            if (km1 == 0 || (diag && kg1 > qgB)) v3 = -INFINITY;
            cs[nf][0] = v0; cs[nf][1] = v1; cs[nf][2] = v2; cs[nf][3] = v3;
        }

#pragma unroll
        for (int ri = 0; ri < 2; ri++) {
            float mx = -INFINITY;
#pragma unroll
            for (int nf = 0; nf < 8; nf++) {
                mx = fmaxf(mx, cs[nf][2 * ri]);
                mx = fmaxf(mx, cs[nf][2 * ri + 1]);
            }
            mx = fmaxf(mx, __shfl_xor_sync(0xffffffffu, mx, 1));
            mx = fmaxf(mx, __shfl_xor_sync(0xffffffffu, mx, 2));

            float mo = m_r[ri];
            float mn = fmaxf(mo, mx);
            float sc, sum = 0.0f;
            if (mn == -INFINITY) {
                sc = 1.0f;
#pragma unroll
                for (int nf = 0; nf < 8; nf++) {
                    cs[nf][2 * ri] = 0.0f;
                    cs[nf][2 * ri + 1] = 0.0f;
                }
            } else {
                sc = __expf(mo - mn);          // mo = -inf -> 0
#pragma unroll
                for (int nf = 0; nf < 8; nf++) {
                    float p0 = __expf(cs[nf][2 * ri] - mn);      // -inf -> 0
                    float p1 = __expf(cs[nf][2 * ri + 1] - mn);
                    cs[nf][2 * ri] = p0;
                    cs[nf][2 * ri + 1] = p1;
                    sum += p0 + p1;
                }
                m_r[ri] = mn;
            }
            sum += __shfl_xor_sync(0xffffffffu, sum, 1);
            sum += __shfl_xor_sync(0xffffffffu, sum, 2);
            l_r[ri] = l_r[ri] * sc + sum;

#pragma unroll
            for (int nf = 0; nf < 8; nf++) {
                o[nf][2 * ri]     *= sc;
                o[nf][2 * ri + 1] *= sc;
            }
            int prow = wrow + g + ri * 8;
#pragma unroll
            for (int nf = 0; nf < 8; nf++) {
                Ps[prow * AT_STRIDE + nf * 8 + 2 * tg]     = __uint_as_float(f2tf32(cs[nf][2 * ri]));
                Ps[prow * AT_STRIDE + nf * 8 + 2 * tg + 1] = __uint_as_float(f2tf32(cs[nf][2 * ri + 1]));
            }
        }
        __syncwarp();

#pragma unroll
        for (int kf = 0; kf < 8; kf++) {
            uint32_t ap[4];
            ap[0] = __float_as_uint(Ps[(wrow + g)     * AT_STRIDE + kf * 8 + tg]);
            ap[1] = __float_as_uint(Ps[(wrow + g + 8) * AT_STRIDE + kf * 8 + tg]);
            ap[2] = __float_as_uint(Ps[(wrow + g)     * AT_STRIDE + kf * 8 + tg + 4]);
            ap[3] = __float_as_uint(Ps[(wrow + g + 8) * AT_STRIDE + kf * 8 + tg + 4]);
#pragma unroll
            for (int nf = 0; nf < 8; nf++) {
                uint32_t bv[2];
                bv[0] = __float_as_uint(Vs[(kf * 8 + tg)     * AT_STRIDE + nf * 8 + g]);
                bv[1] = __float_as_uint(Vs[(kf * 8 + tg + 4) * AT_STRIDE + nf * 8 + g]);
                mma_tf32(o[nf], ap, bv);
            }
        }
        __syncwarp();   // P slab reads done before next-tile overwrite
    }

#pragma unroll
    for (int ri = 0; ri < 2; ri++) {
        int r_loc = wrow + g + ri * 8;
        int qg    = q0 + r_loc;
        int qmv   = qmask[b * SEQ + qg];
        float l   = l_r[ri];
        float* dst = g_At + (size_t)(b * SEQ + qg) * D_MODEL + h * D_K;
#pragma unroll
        for (int nf = 0; nf < 8; nf++) {
            float v0 = o[nf][2 * ri]     / l;
            float v1 = o[nf][2 * ri + 1] / l;
            if (qmv == 0) { v0 = 0.0f; v1 = 0.0f; }
            float2 pr = make_float2(v0, v1);
            *(float2*)&dst[nf * 8 + 2 * tg] = pr;
        }
    }
}

// ---------------------------------------------------------------------------
extern "C" void kernel_launch(void* const* d_in, const int* in_sizes, int n_in,
                              void* d_out, int out_size)
{
    const float* q  = (const float*)d_in[0];
    const float* k  = (const float*)d_in[1];
    const int*   qm = (const int*)  d_in[2];
    const int*   km = (const int*)  d_in[3];
    const float* Wq = (const float*)d_in[4];
    const float* bq = (const float*)d_in[5];
    const float* Wk = (const float*)d_in[6];
    const float* bk = (const float*)d_in[7];
    const float* Wv = (const float*)d_in[8];
    const float* bv = (const float*)d_in[9];
    const float* Wo = (const float*)d_in[10];
    const float* bo = (const float*)d_in[11];
    const int*   cz = (const int*)  d_in[12];
    float* out = (float*)d_out;

    float *Qh, *Kh, *Vh, *At;
    cudaGetSymbolAddress((void**)&Qh, g_Qh);
    cudaGetSymbolAddress((void**)&Kh, g_Kh);
    cudaGetSymbolAddress((void**)&Vh, g_Vh);
    cudaGetSymbolAddress((void**)&At, g_At);

    cudaFuncSetAttribute(gemm_proj3_kernel, cudaFuncAttributeMaxDynamicSharedMemorySize, GEMM_SMEM_BYTES);
    cudaFuncSetAttribute(gemm_out_kernel,   cudaFuncAttributeMaxDynamicSharedMemorySize, GEMM_SMEM_BYTES);

    // Batched Q/K/V projections (one launch, z = which GEMM)
    dim3 pgrid(D_MODEL / 128, M_ROWS / 128, 3);   // (8, 32, 3)
    gemm_proj3_kernel<<<pgrid, 256, GEMM_SMEM_BYTES>>>(q, k, Wq, bq, Wk, bk, Wv, bv, Qh, Kh, Vh);

    // Tensor-core flash attention
    size_t smem = (size_t)(3 * 64 * AT_STRIDE) * sizeof(float) + 64 * sizeof(int);
    cudaFuncSetAttribute(attn_mma_kernel, cudaFuncAttributeMaxDynamicSharedMemorySize, (int)smem);
    attn_mma_kernel<<<dim3(SEQ / 64, B_SZ * NHEAD), 128, smem>>>(qm, km, cz);

    // Output projection
    dim3 ogrid(D_MODEL / 128, M_ROWS / 128);      // (8, 32)
    gemm_out_kernel<<<ogrid, 256, GEMM_SMEM_BYTES>>>(At, Wo, bo, out);
}

// round 13
// speedup vs baseline: 1.4734x; 1.4734x over previous
#include <cuda_runtime.h>
#include <cuda_bf16.h>
#include <math.h>
#include <stdint.h>

// Problem constants
#define D_MODEL 1024
#define NHEAD   16
#define D_K     64
#define B_SZ    2
#define SEQ     2048
#define M_ROWS  (B_SZ * SEQ)        // 4096

// Scratch (allocation-free rule: __device__ globals)
__device__ float g_Qh[B_SZ * NHEAD * SEQ * D_K];   // [B,H,S,64]
__device__ float g_Kh[B_SZ * NHEAD * SEQ * D_K];
__device__ float g_Vh[B_SZ * NHEAD * SEQ * D_K];
__device__ float g_At[B_SZ * SEQ * D_MODEL];       // [B,S,D] merged heads

__device__ __forceinline__ uint32_t f2tf32(float x) {
    uint32_t r;
    asm("cvt.rna.tf32.f32 %0, %1;" : "=r"(r) : "f"(x));
    return r;
}

__device__ __forceinline__ void mma_tf32(float c[4], const uint32_t a[4], const uint32_t b[2]) {
    asm volatile(
        "mma.sync.aligned.m16n8k8.row.col.f32.tf32.tf32.f32 "
        "{%0,%1,%2,%3}, {%4,%5,%6,%7}, {%8,%9}, {%0,%1,%2,%3};"
        : "+f"(c[0]), "+f"(c[1]), "+f"(c[2]), "+f"(c[3])
        : "r"(a[0]), "r"(a[1]), "r"(a[2]), "r"(a[3]),
          "r"(b[0]), "r"(b[1]));
}

__device__ __forceinline__ uint32_t smem_u32(const void* p) {
    uint32_t a;
    asm("{ .reg .u64 t; cvta.to.shared.u64 t, %1; cvt.u32.u64 %0, t; }" : "=r"(a) : "l"(p));
    return a;
}

#define CP_ASYNC16(dst_u32, src_ptr) \
    asm volatile("cp.async.cg.shared.global [%0], [%1], 16;" \
                 :: "r"(dst_u32), "l"(src_ptr) : "memory")
#define CP_COMMIT() asm volatile("cp.async.commit_group;" ::: "memory")
#define CP_WAIT(n)  asm volatile("cp.async.wait_group %0;" :: "n"(n) : "memory")

// ---------------------------------------------------------------------------
// cp.async-pipelined TF32 GEMM:  C[M,N] = A[M,K] @ W[N,K]^T + bias[N]
// Block tile 128x128, BK=32, 256 threads = 8 warps (warp tile 64x32).
// Chunk ch+1 streams global->smem via LDGSTS (zero register cost) while the
// 64 MMAs of chunk ch run. 2 CTAs/SM preserved (regs capped at 128).
// MODE 0: row-major [M,N].  MODE 1: head-split [B,H,S,64].
// ---------------------------------------------------------------------------
#define SM_STRIDE 36
#define GEMM_SMEM_BYTES (4 * 128 * SM_STRIDE * 4)   // 73728 B (2 bufs x (A+W))

template <int MODE>
__device__ __forceinline__
void gemm_body(const float* __restrict__ A,
               const float* __restrict__ W,
               const float* __restrict__ bias,
               float* __restrict__ C,
               int m0, int n0)
{
    extern __shared__ float gsm[];
    float* const bufs[2][2] = {
        { gsm,                      gsm + 128 * SM_STRIDE },       // buf0: A, W
        { gsm + 2 * 128 * SM_STRIDE, gsm + 3 * 128 * SM_STRIDE }   // buf1: A, W
    };

    const int tid  = threadIdx.x;
    const int warp = tid >> 5;
    const int lane = tid & 31;
    const int g    = lane >> 2;
    const int tg   = lane & 3;

    const int wm = (warp & 1) * 64;
    const int wn = (warp >> 1) * 32;

    // staging coords: thread covers rows (tid>>3)+32*i, 16B col block (tid&7)
    const int srow = tid >> 3;
    const int sc4  = (tid & 7) * 4;
    const float* Aptr = A + (size_t)(m0 + srow) * D_MODEL + sc4;
    const float* Wptr = W + (size_t)(n0 + srow) * D_MODEL + sc4;
    const uint32_t stA0 = smem_u32(bufs[0][0]) + (uint32_t)(srow * SM_STRIDE + sc4) * 4;
    const uint32_t stW0 = smem_u32(bufs[0][1]) + (uint32_t)(srow * SM_STRIDE + sc4) * 4;
    const uint32_t stA1 = smem_u32(bufs[1][0]) + (uint32_t)(srow * SM_STRIDE + sc4) * 4;
    const uint32_t stW1 = smem_u32(bufs[1][1]) + (uint32_t)(srow * SM_STRIDE + sc4) * 4;
    const uint32_t rowB = 32 * SM_STRIDE * 4;   // byte stride for 32 rows

    float c[4][4][4];
#pragma unroll
    for (int mi = 0; mi < 4; mi++)
#pragma unroll
        for (int ni = 0; ni < 4; ni++)
#pragma unroll
            for (int r = 0; r < 4; r++) c[mi][ni][r] = 0.0f;

    // prologue: chunk 0 -> buf0
#pragma unroll
    for (int i = 0; i < 4; i++) {
        CP_ASYNC16(stA0 + i * rowB, &Aptr[(size_t)(i * 32) * D_MODEL]);
        CP_ASYNC16(stW0 + i * rowB, &Wptr[(size_t)(i * 32) * D_MODEL]);
    }
    CP_COMMIT();

    for (int ch = 0; ch < D_MODEL / 32; ch++) {
        // issue chunk ch+1 into the other buffer (safe: trailing sync of
        // iter ch-1 proved all warps finished computing from it)
        if (ch + 1 < D_MODEL / 32) {
            const int k1 = (ch + 1) * 32;
            const uint32_t dA = ((ch + 1) & 1) ? stA1 : stA0;
            const uint32_t dW = ((ch + 1) & 1) ? stW1 : stW0;
#pragma unroll
            for (int i = 0; i < 4; i++) {
                CP_ASYNC16(dA + i * rowB, &Aptr[(size_t)(i * 32) * D_MODEL + k1]);
                CP_ASYNC16(dW + i * rowB, &Wptr[(size_t)(i * 32) * D_MODEL + k1]);
            }
            CP_COMMIT();
            CP_WAIT(1);        // chunk ch complete, ch+1 in flight
        } else {
            CP_WAIT(0);
        }
        __syncthreads();

        const float* const as = bufs[ch & 1][0];
        const float* const ws = bufs[ch & 1][1];

#pragma unroll
        for (int kk = 0; kk < 32; kk += 8) {
            uint32_t a[4][4], b[4][2];
#pragma unroll
            for (int mi = 0; mi < 4; mi++) {
                int r = wm + mi * 16 + g;
                a[mi][0] = f2tf32(as[r * SM_STRIDE + kk + tg]);
                a[mi][1] = f2tf32(as[(r + 8) * SM_STRIDE + kk + tg]);
                a[mi][2] = f2tf32(as[r * SM_STRIDE + kk + tg + 4]);
                a[mi][3] = f2tf32(as[(r + 8) * SM_STRIDE + kk + tg + 4]);
            }
#pragma unroll
            for (int ni = 0; ni < 4; ni++) {
                int cn = wn + ni * 8 + g;
                b[ni][0] = f2tf32(ws[cn * SM_STRIDE + kk + tg]);
                b[ni][1] = f2tf32(ws[cn * SM_STRIDE + kk + tg + 4]);
            }
#pragma unroll
            for (int mi = 0; mi < 4; mi++)
#pragma unroll
                for (int ni = 0; ni < 4; ni++)
                    mma_tf32(c[mi][ni], a[mi], b[ni]);
        }
        __syncthreads();   // all warps done with this buffer before overwrite
    }

    // Epilogue: add bias, store.
#pragma unroll
    for (int mi = 0; mi < 4; mi++) {
#pragma unroll
        for (int ni = 0; ni < 4; ni++) {
            int row = m0 + wm + mi * 16 + g;
            int col = n0 + wn + ni * 8 + 2 * tg;
#pragma unroll
            for (int rr = 0; rr < 2; rr++) {
                int m = row + rr * 8;
#pragma unroll
                for (int cc = 0; cc < 2; cc++) {
                    int n = col + cc;
                    float v = c[mi][ni][rr * 2 + cc] + bias[n];
                    if (MODE == 0) {
                        C[(size_t)m * D_MODEL + n] = v;
                    } else {
                        int bb = m >> 11;
                        int s  = m & 2047;
                        int h  = n >> 6;
                        int d  = n & 63;
                        C[(((size_t)(bb * NHEAD + h) * SEQ) + s) * D_K + d] = v;
                    }
                }
            }
        }
    }
}

// Batched Q/K/V projection: blockIdx.z selects which GEMM.
__global__ __launch_bounds__(256, 2)
void gemm_proj3_kernel(const float* __restrict__ q,
                       const float* __restrict__ k,
                       const float* __restrict__ Wq, const float* __restrict__ bq,
                       const float* __restrict__ Wk, const float* __restrict__ bk,
                       const float* __restrict__ Wv, const float* __restrict__ bv,
                       float* __restrict__ Qh, float* __restrict__ Kh,
                       float* __restrict__ Vh)
{
    const int z = blockIdx.z;
    const float* A    = (z == 0) ? q  : k;
    const float* W    = (z == 0) ? Wq : (z == 1) ? Wk : Wv;
    const float* bias = (z == 0) ? bq : (z == 1) ? bk : bv;
    float*       C    = (z == 0) ? Qh : (z == 1) ? Kh : Vh;
    gemm_body<1>(A, W, bias, C, blockIdx.y * 128, blockIdx.x * 128);
}

// Output projection (row-major out).
__global__ __launch_bounds__(256, 2)
void gemm_out_kernel(const float* __restrict__ A,
                     const float* __restrict__ W,
                     const float* __restrict__ bias,
                     float* __restrict__ C)
{
    gemm_body<0>(A, W, bias, C, blockIdx.y * 128, blockIdx.x * 128);
}

// ---------------------------------------------------------------------------
// Tensor-core flash attention (proven version, unchanged).
// Block: 128 threads (4 warps), 64 query rows. Key tiles of 64.
// ---------------------------------------------------------------------------
#define AT_STRIDE 68   // floats; bank = 4g+tg permutation -> conflict-free frags

__global__ __launch_bounds__(128)
void attn_mma_kernel(const int* __restrict__ qmask,
                     const int* __restrict__ kmask,
                     const int* __restrict__ causal_flag)
{
    extern __shared__ float sm[];
    float* Ps  = sm;                         // 64*AT_STRIDE (Q staging, then P)
    float* Ks  = Ps + 64 * AT_STRIDE;        // tf32-converted K tile [key][d]
    float* Vs  = Ks + 64 * AT_STRIDE;        // tf32-converted V tile [key][d]
    int*   km_s = (int*)(Vs + 64 * AT_STRIDE);

    const int tid  = threadIdx.x;
    const int warp = tid >> 5;
    const int lane = tid & 31;
    const int g    = lane >> 2;
    const int tg   = lane & 3;
    const int wrow = warp * 16;

    const int qt = (gridDim.x - 1) - blockIdx.x;   // longest blocks first
    const int bh = blockIdx.y;
    const int b  = bh >> 4;
    const int h  = bh & 15;
    const int q0 = qt * 64;
    const int causal = causal_flag[0];
    const size_t head_base = (size_t)bh * SEQ * D_K;

    {
        const float* qsrc = g_Qh + head_base + (size_t)q0 * D_K;
#pragma unroll
        for (int i = 0; i < 8; i++) {
            int lin = tid + i * 128;
            int r   = lin >> 4;
            int c4  = (lin & 15) * 4;
            float4 v = *(const float4*)&qsrc[r * 64 + c4];
            *(float4*)&Ps[r * AT_STRIDE + c4] = v;
        }
    }
    __syncthreads();

    uint32_t aq[8][4];
#pragma unroll
    for (int kf = 0; kf < 8; kf++) {
        int c = kf * 8;
        aq[kf][0] = f2tf32(Ps[(wrow + g)     * AT_STRIDE + c + tg]);
        aq[kf][1] = f2tf32(Ps[(wrow + g + 8) * AT_STRIDE + c + tg]);
        aq[kf][2] = f2tf32(Ps[(wrow + g)     * AT_STRIDE + c + tg + 4]);
        aq[kf][3] = f2tf32(Ps[(wrow + g + 8) * AT_STRIDE + c + tg + 4]);
    }

    float m_r[2] = { -INFINITY, -INFINITY };
    float l_r[2] = { 0.0f, 0.0f };
    float o[8][4];
#pragma unroll
    for (int nf = 0; nf < 8; nf++)
#pragma unroll
        for (int r = 0; r < 4; r++) o[nf][r] = 0.0f;

    const int ntiles = causal ? (qt + 1) : (SEQ / 64);

    for (int kt = 0; kt < ntiles; kt++) {
        const int k0 = kt * 64;
        __syncthreads();   // previous tile's MMA reads of Ks/Vs done
        {
            const float* ksrc = g_Kh + head_base + (size_t)k0 * D_K;
            const float* vsrc = g_Vh + head_base + (size_t)k0 * D_K;
#pragma unroll
            for (int i = 0; i < 8; i++) {
                int lin = tid + i * 128;
                int r   = lin >> 4;
                int c4  = (lin & 15) * 4;
                float4 kv = *(const float4*)&ksrc[r * 64 + c4];
                kv.x = __uint_as_float(f2tf32(kv.x));
                kv.y = __uint_as_float(f2tf32(kv.y));
                kv.z = __uint_as_float(f2tf32(kv.z));
                kv.w = __uint_as_float(f2tf32(kv.w));
                *(float4*)&Ks[r * AT_STRIDE + c4] = kv;
                float4 vv = *(const float4*)&vsrc[r * 64 + c4];
                vv.x = __uint_as_float(f2tf32(vv.x));
                vv.y = __uint_as_float(f2tf32(vv.y));
                vv.z = __uint_as_float(f2tf32(vv.z));
                vv.w = __uint_as_float(f2tf32(vv.w));
                *(float4*)&Vs[r * AT_STRIDE + c4] = vv;
            }
            if (tid < 64) km_s[tid] = kmask[b * SEQ + k0 + tid];
        }
        __syncthreads();

        float cs[8][4];
#pragma unroll
        for (int nf = 0; nf < 8; nf++)
#pragma unroll
            for (int r = 0; r < 4; r++) cs[nf][r] = 0.0f;

#pragma unroll
        for (int kf = 0; kf < 8; kf++) {
            uint32_t bk[8][2];
#pragma unroll
            for (int nf = 0; nf < 8; nf++) {
                bk[nf][0] = __float_as_uint(Ks[(nf * 8 + g) * AT_STRIDE + kf * 8 + tg]);
                bk[nf][1] = __float_as_uint(Ks[(nf * 8 + g) * AT_STRIDE + kf * 8 + tg + 4]);
            }
#pragma unroll
            for (int nf = 0; nf < 8; nf++)
                mma_tf32(cs[nf], aq[kf], bk[nf]);
        }

        const bool diag = (causal != 0) && (kt == qt);
        const int qgA = q0 + wrow + g;
        const int qgB = qgA + 8;
#pragma unroll
        for (int nf = 0; nf < 8; nf++) {
            int colb = nf * 8 + 2 * tg;
            int km0 = km_s[colb];
            int km1 = km_s[colb + 1];
            int kg0 = k0 + colb;
            int kg1 = kg0 + 1;
            float v0 = cs[nf][0] * 0.125f;
            float v1 = cs[nf][1] * 0.125f;
            float v2 = cs[nf][2] * 0.125f;
            float v3 = cs[nf][3] * 0.125f;
            if (km0 == 0 || (diag && kg0 > qgA)) v0 = -INFINITY;
            if (km1 == 0 || (diag && kg1 > qgA)) v1 = -INFINITY;
            if (km0 == 0 || (diag && kg0 > qgB)) v2 = -INFINITY;
            if (km1 == 0 || (diag && kg1 > qgB)) v3 = -INFINITY;
            cs[nf][0] = v0; cs[nf][1] = v1; cs[nf][2] = v2; cs[nf][3] = v3;
        }

#pragma unroll
        for (int ri = 0; ri < 2; ri++) {
            float mx = -INFINITY;
#pragma unroll
            for (int nf = 0; nf < 8; nf++) {
                mx = fmaxf(mx, cs[nf][2 * ri]);
                mx = fmaxf(mx, cs[nf][2 * ri + 1]);
            }
            mx = fmaxf(mx, __shfl_xor_sync(0xffffffffu, mx, 1));
            mx = fmaxf(mx, __shfl_xor_sync(0xffffffffu, mx, 2));

            float mo = m_r[ri];
            float mn = fmaxf(mo, mx);
            float sc, sum = 0.0f;
            if (mn == -INFINITY) {
                sc = 1.0f;
#pragma unroll
                for (int nf = 0; nf < 8; nf++) {
                    cs[nf][2 * ri] = 0.0f;
                    cs[nf][2 * ri + 1] = 0.0f;
                }
            } else {
                sc = __expf(mo - mn);          // mo = -inf -> 0
#pragma unroll
                for (int nf = 0; nf < 8; nf++) {
                    float p0 = __expf(cs[nf][2 * ri] - mn);      // -inf -> 0
                    float p1 = __expf(cs[nf][2 * ri + 1] - mn);
                    cs[nf][2 * ri] = p0;
                    cs[nf][2 * ri + 1] = p1;
                    sum += p0 + p1;
                }
                m_r[ri] = mn;
            }
            sum += __shfl_xor_sync(0xffffffffu, sum, 1);
            sum += __shfl_xor_sync(0xffffffffu, sum, 2);
            l_r[ri] = l_r[ri] * sc + sum;

#pragma unroll
            for (int nf = 0; nf < 8; nf++) {
                o[nf][2 * ri]     *= sc;
                o[nf][2 * ri + 1] *= sc;
            }
            int prow = wrow + g + ri * 8;
#pragma unroll
            for (int nf = 0; nf < 8; nf++) {
                Ps[prow * AT_STRIDE + nf * 8 + 2 * tg]     = __uint_as_float(f2tf32(cs[nf][2 * ri]));
                Ps[prow * AT_STRIDE + nf * 8 + 2 * tg + 1] = __uint_as_float(f2tf32(cs[nf][2 * ri + 1]));
            }
        }
        __syncwarp();

#pragma unroll
        for (int kf = 0; kf < 8; kf++) {
            uint32_t ap[4];
            ap[0] = __float_as_uint(Ps[(wrow + g)     * AT_STRIDE + kf * 8 + tg]);
            ap[1] = __float_as_uint(Ps[(wrow + g + 8) * AT_STRIDE + kf * 8 + tg]);
            ap[2] = __float_as_uint(Ps[(wrow + g)     * AT_STRIDE + kf * 8 + tg + 4]);
            ap[3] = __float_as_uint(Ps[(wrow + g + 8) * AT_STRIDE + kf * 8 + tg + 4]);
#pragma unroll
            for (int nf = 0; nf < 8; nf++) {
                uint32_t bv[2];
                bv[0] = __float_as_uint(Vs[(kf * 8 + tg)     * AT_STRIDE + nf * 8 + g]);
                bv[1] = __float_as_uint(Vs[(kf * 8 + tg + 4) * AT_STRIDE + nf * 8 + g]);
                mma_tf32(o[nf], ap, bv);
            }
        }
        __syncwarp();   // P slab reads done before next-tile overwrite
    }

#pragma unroll
    for (int ri = 0; ri < 2; ri++) {
        int r_loc = wrow + g + ri * 8;
        int qg    = q0 + r_loc;
        int qmv   = qmask[b * SEQ + qg];
        float l   = l_r[ri];
        float* dst = g_At + (size_t)(b * SEQ + qg) * D_MODEL + h * D_K;
#pragma unroll
        for (int nf = 0; nf < 8; nf++) {
            float v0 = o[nf][2 * ri]     / l;
            float v1 = o[nf][2 * ri + 1] / l;
            if (qmv == 0) { v0 = 0.0f; v1 = 0.0f; }
            float2 pr = make_float2(v0, v1);
            *(float2*)&dst[nf * 8 + 2 * tg] = pr;
        }
    }
}

// ---------------------------------------------------------------------------
extern "C" void kernel_launch(void* const* d_in, const int* in_sizes, int n_in,
                              void* d_out, int out_size)
{
    const float* q  = (const float*)d_in[0];
    const float* k  = (const float*)d_in[1];
    const int*   qm = (const int*)  d_in[2];
    const int*   km = (const int*)  d_in[3];
    const float* Wq = (const float*)d_in[4];
    const float* bq = (const float*)d_in[5];
    const float* Wk = (const float*)d_in[6];
    const float* bk = (const float*)d_in[7];
    const float* Wv = (const float*)d_in[8];
    const float* bv = (const float*)d_in[9];
    const float* Wo = (const float*)d_in[10];
    const float* bo = (const float*)d_in[11];
    const int*   cz = (const int*)  d_in[12];
    float* out = (float*)d_out;

    float *Qh, *Kh, *Vh, *At;
    cudaGetSymbolAddress((void**)&Qh, g_Qh);
    cudaGetSymbolAddress((void**)&Kh, g_Kh);
    cudaGetSymbolAddress((void**)&Vh, g_Vh);
    cudaGetSymbolAddress((void**)&At, g_At);

    cudaFuncSetAttribute(gemm_proj3_kernel, cudaFuncAttributeMaxDynamicSharedMemorySize, GEMM_SMEM_BYTES);
    cudaFuncSetAttribute(gemm_out_kernel,   cudaFuncAttributeMaxDynamicSharedMemorySize, GEMM_SMEM_BYTES);

    // Batched Q/K/V projections (one launch, z = which GEMM)
    dim3 pgrid(D_MODEL / 128, M_ROWS / 128, 3);   // (8, 32, 3)
    gemm_proj3_kernel<<<pgrid, 256, GEMM_SMEM_BYTES>>>(q, k, Wq, bq, Wk, bk, Wv, bv, Qh, Kh, Vh);

    // Tensor-core flash attention
    size_t smem = (size_t)(3 * 64 * AT_STRIDE) * sizeof(float) + 64 * sizeof(int);
    cudaFuncSetAttribute(attn_mma_kernel, cudaFuncAttributeMaxDynamicSharedMemorySize, (int)smem);
    attn_mma_kernel<<<dim3(SEQ / 64, B_SZ * NHEAD), 128, smem>>>(qm, km, cz);

    // Output projection
    dim3 ogrid(D_MODEL / 128, M_ROWS / 128);      // (8, 32)
    gemm_out_kernel<<<ogrid, 256, GEMM_SMEM_BYTES>>>(At, Wo, bo, out);
}

// round 14
// speedup vs baseline: 1.9703x; 1.3372x over previous
#include <cuda_runtime.h>
#include <cuda_bf16.h>
#include <math.h>
#include <stdint.h>

// Problem constants
#define D_MODEL 1024
#define NHEAD   16
#define D_K     64
#define B_SZ    2
#define SEQ     2048
#define M_ROWS  (B_SZ * SEQ)        // 4096

// Scratch (allocation-free rule: __device__ globals)
__device__ float g_Qh[B_SZ * NHEAD * SEQ * D_K];   // [B,H,S,64]
__device__ float g_Kh[B_SZ * NHEAD * SEQ * D_K];
__device__ float g_Vh[B_SZ * NHEAD * SEQ * D_K];
__device__ float g_At[B_SZ * SEQ * D_MODEL];       // [B,S,D] merged heads

__device__ __forceinline__ uint32_t f2tf32(float x) {
    uint32_t r;
    asm("cvt.rna.tf32.f32 %0, %1;" : "=r"(r) : "f"(x));
    return r;
}

__device__ __forceinline__ uint32_t pack_f16x2(float lo, float hi) {
    uint32_t r;
    asm("cvt.rn.f16x2.f32 %0, %1, %2;" : "=r"(r) : "f"(hi), "f"(lo));  // d.lo=%2
    return r;
}

__device__ __forceinline__ void mma_tf32(float c[4], const uint32_t a[4], const uint32_t b[2]) {
    asm volatile(
        "mma.sync.aligned.m16n8k8.row.col.f32.tf32.tf32.f32 "
        "{%0,%1,%2,%3}, {%4,%5,%6,%7}, {%8,%9}, {%0,%1,%2,%3};"
        : "+f"(c[0]), "+f"(c[1]), "+f"(c[2]), "+f"(c[3])
        : "r"(a[0]), "r"(a[1]), "r"(a[2]), "r"(a[3]),
          "r"(b[0]), "r"(b[1]));
}

__device__ __forceinline__ void mma_f16(float c[4], const uint32_t a[4],
                                        uint32_t b0, uint32_t b1) {
    asm volatile(
        "mma.sync.aligned.m16n8k16.row.col.f32.f16.f16.f32 "
        "{%0,%1,%2,%3}, {%4,%5,%6,%7}, {%8,%9}, {%0,%1,%2,%3};"
        : "+f"(c[0]), "+f"(c[1]), "+f"(c[2]), "+f"(c[3])
        : "r"(a[0]), "r"(a[1]), "r"(a[2]), "r"(a[3]),
          "r"(b0), "r"(b1));
}

__device__ __forceinline__ void ldsm_x4(uint32_t& r0, uint32_t& r1, uint32_t& r2,
                                        uint32_t& r3, uint32_t addr) {
    asm volatile("ldmatrix.sync.aligned.m8n8.x4.shared.b16 {%0,%1,%2,%3}, [%4];"
                 : "=r"(r0), "=r"(r1), "=r"(r2), "=r"(r3) : "r"(addr));
}

__device__ __forceinline__ void ldsm_x4_trans(uint32_t& r0, uint32_t& r1, uint32_t& r2,
                                              uint32_t& r3, uint32_t addr) {
    asm volatile("ldmatrix.sync.aligned.m8n8.x4.trans.shared.b16 {%0,%1,%2,%3}, [%4];"
                 : "=r"(r0), "=r"(r1), "=r"(r2), "=r"(r3) : "r"(addr));
}

__device__ __forceinline__ uint32_t smem_u32(const void* p) {
    uint32_t a;
    asm("{ .reg .u64 t; cvta.to.shared.u64 t, %1; cvt.u32.u64 %0, t; }" : "=r"(a) : "l"(p));
    return a;
}

// ---------------------------------------------------------------------------
// TF32 tensor-core GEMM body (exact R10 proven version):
// C[M,N] = A[M,K] @ W[N,K]^T + bias[N].  128x128 tile, BK=32, 256 thr.
// MODE 0: row-major [M,N].  MODE 1: head-split [B,H,S,64].
// ---------------------------------------------------------------------------
#define SM_STRIDE 44

template <int MODE>
__device__ __forceinline__
void gemm_body(const float* __restrict__ A,
               const float* __restrict__ W,
               const float* __restrict__ bias,
               float* __restrict__ C,
               int m0, int n0)
{
    __shared__ uint32_t As[128 * SM_STRIDE];
    __shared__ uint32_t Ws[128 * SM_STRIDE];

    const int tid  = threadIdx.x;
    const int warp = tid >> 5;
    const int lane = tid & 31;
    const int g    = lane >> 2;
    const int tg   = lane & 3;

    const int wm = (warp & 1) * 64;
    const int wn = (warp >> 1) * 32;

    float c[4][4][4];
#pragma unroll
    for (int mi = 0; mi < 4; mi++)
#pragma unroll
        for (int ni = 0; ni < 4; ni++)
#pragma unroll
            for (int r = 0; r < 4; r++) c[mi][ni][r] = 0.0f;

    for (int k0 = 0; k0 < D_MODEL; k0 += 32) {
#pragma unroll
        for (int i = 0; i < 4; i++) {
            int idx = tid + i * 256;
            int r   = idx >> 3;
            int c4  = idx & 7;
            float4 va = *(const float4*)&A[(size_t)(m0 + r) * D_MODEL + k0 + c4 * 4];
            uint4 ua = make_uint4(f2tf32(va.x), f2tf32(va.y), f2tf32(va.z), f2tf32(va.w));
            *(uint4*)&As[r * SM_STRIDE + c4 * 4] = ua;
            float4 vw = *(const float4*)&W[(size_t)(n0 + r) * D_MODEL + k0 + c4 * 4];
            uint4 uw = make_uint4(f2tf32(vw.x), f2tf32(vw.y), f2tf32(vw.z), f2tf32(vw.w));
            *(uint4*)&Ws[r * SM_STRIDE + c4 * 4] = uw;
        }
        __syncthreads();

#pragma unroll
        for (int kk = 0; kk < 32; kk += 8) {
            uint32_t a[4][4], b[4][2];
#pragma unroll
            for (int mi = 0; mi < 4; mi++) {
                int r = wm + mi * 16 + g;
                a[mi][0] = As[r * SM_STRIDE + kk + tg];
                a[mi][1] = As[(r + 8) * SM_STRIDE + kk + tg];
                a[mi][2] = As[r * SM_STRIDE + kk + tg + 4];
                a[mi][3] = As[(r + 8) * SM_STRIDE + kk + tg + 4];
            }
#pragma unroll
            for (int ni = 0; ni < 4; ni++) {
                int cn = wn + ni * 8 + g;
                b[ni][0] = Ws[cn * SM_STRIDE + kk + tg];
                b[ni][1] = Ws[cn * SM_STRIDE + kk + tg + 4];
            }
#pragma unroll
            for (int mi = 0; mi < 4; mi++)
#pragma unroll
                for (int ni = 0; ni < 4; ni++)
                    mma_tf32(c[mi][ni], a[mi], b[ni]);
        }
        __syncthreads();
    }

#pragma unroll
    for (int mi = 0; mi < 4; mi++) {
#pragma unroll
        for (int ni = 0; ni < 4; ni++) {
            int row = m0 + wm + mi * 16 + g;
            int col = n0 + wn + ni * 8 + 2 * tg;
#pragma unroll
            for (int rr = 0; rr < 2; rr++) {
                int m = row + rr * 8;
#pragma unroll
                for (int cc = 0; cc < 2; cc++) {
                    int n = col + cc;
                    float v = c[mi][ni][rr * 2 + cc] + bias[n];
                    if (MODE == 0) {
                        C[(size_t)m * D_MODEL + n] = v;
                    } else {
                        int bb = m >> 11;
                        int s  = m & 2047;
                        int h  = n >> 6;
                        int d  = n & 63;
                        C[(((size_t)(bb * NHEAD + h) * SEQ) + s) * D_K + d] = v;
                    }
                }
            }
        }
    }
}

__global__ __launch_bounds__(256, 2)
void gemm_proj3_kernel(const float* __restrict__ q,
                       const float* __restrict__ k,
                       const float* __restrict__ Wq, const float* __restrict__ bq,
                       const float* __restrict__ Wk, const float* __restrict__ bk,
                       const float* __restrict__ Wv, const float* __restrict__ bv,
                       float* __restrict__ Qh, float* __restrict__ Kh,
                       float* __restrict__ Vh)
{
    const int z = blockIdx.z;
    const float* A    = (z == 0) ? q  : k;
    const float* W    = (z == 0) ? Wq : (z == 1) ? Wk : Wv;
    const float* bias = (z == 0) ? bq : (z == 1) ? bk : bv;
    float*       C    = (z == 0) ? Qh : (z == 1) ? Kh : Vh;
    gemm_body<1>(A, W, bias, C, blockIdx.y * 128, blockIdx.x * 128);
}

__global__ __launch_bounds__(256, 2)
void gemm_out_kernel(const float* __restrict__ A,
                     const float* __restrict__ W,
                     const float* __restrict__ bias,
                     float* __restrict__ C)
{
    gemm_body<0>(A, W, bias, C, blockIdx.y * 128, blockIdx.x * 128);
}

// ---------------------------------------------------------------------------
// f16 flash attention: m16n8k16 MMA, ldmatrix operand loads, P in registers.
// Block: 128 threads (4 warps), 64 query rows; key tiles of 64.
// Q/K/V staged as f16 [row][72] (144B row stride -> conflict-free ldmatrix).
// Softmax in fp32 registers (unchanged semantics incl. all-masked -> NaN).
// ---------------------------------------------------------------------------
#define HST 72   // halves per smem row (144 B)

__global__ __launch_bounds__(128)
void attn_mma_kernel(const int* __restrict__ qmask,
                     const int* __restrict__ kmask,
                     const int* __restrict__ causal_flag)
{
    __shared__ __align__(16) uint16_t Qs[64 * HST];
    __shared__ __align__(16) uint16_t Ks[64 * HST];
    __shared__ __align__(16) uint16_t Vs[64 * HST];
    __shared__ int km_s[64];

    const int tid  = threadIdx.x;
    const int warp = tid >> 5;
    const int lane = tid & 31;
    const int g    = lane >> 2;
    const int tg   = lane & 3;
    const int wrow = warp * 16;

    const int qt = (gridDim.x - 1) - blockIdx.x;   // longest blocks first
    const int bh = blockIdx.y;
    const int b  = bh >> 4;
    const int h  = bh & 15;
    const int q0 = qt * 64;
    const int causal = causal_flag[0];
    const size_t head_base = (size_t)bh * SEQ * D_K;

    const uint32_t QsB = smem_u32(Qs);
    const uint32_t KsB = smem_u32(Ks);
    const uint32_t VsB = smem_u32(Vs);

    // ldmatrix per-lane base offsets (bytes within a tile)
    const int li = lane >> 3;          // matrix index 0..3
    const int lr = lane & 7;           // row within matrix
    // Q (A-frags):  m bit0 -> row+8, bit1 -> col+8 halves
    const uint32_t offQ = (uint32_t)((lr + (li & 1) * 8) * (HST * 2) + (li >> 1) * 16);
    // K (B-frags, QK): m bit0 -> col+8 halves, bit1 -> row(key)+8
    const uint32_t offK = (uint32_t)((lr + (li >> 1) * 8) * (HST * 2) + (li & 1) * 16);
    // V (B-frags via .trans, PV): m bit0 -> row(key)+8, bit1 -> col(d)+8
    const uint32_t offV = (uint32_t)((lr + (li & 1) * 8) * (HST * 2) + (li >> 1) * 16);

    // Stage Q tile -> f16
    {
        const float* qsrc = g_Qh + head_base + (size_t)q0 * D_K;
#pragma unroll
        for (int i = 0; i < 8; i++) {
            int lin = tid + i * 128;
            int r   = lin >> 4;
            int c4  = (lin & 15) * 4;
            float4 v = *(const float4*)&qsrc[r * 64 + c4];
            uint32_t u0 = pack_f16x2(v.x, v.y);
            uint32_t u1 = pack_f16x2(v.z, v.w);
            asm volatile("st.shared.v2.b32 [%0], {%1,%2};"
                         :: "r"(QsB + (uint32_t)(r * HST + c4) * 2), "r"(u0), "r"(u1));
        }
    }
    __syncthreads();

    // Q A-fragments (4 k16-chunks x 4 regs), reused for every key tile
    uint32_t aq[4][4];
#pragma unroll
    for (int j = 0; j < 4; j++)
        ldsm_x4(aq[j][0], aq[j][1], aq[j][2], aq[j][3],
                QsB + (uint32_t)(wrow * (HST * 2)) + offQ + (uint32_t)(j * 32));

    float m_r[2] = { -INFINITY, -INFINITY };
    float l_r[2] = { 0.0f, 0.0f };
    float o[8][4];
#pragma unroll
    for (int nf = 0; nf < 8; nf++)
#pragma unroll
        for (int r = 0; r < 4; r++) o[nf][r] = 0.0f;

    const int ntiles = causal ? (qt + 1) : (SEQ / 64);

    for (int kt = 0; kt < ntiles; kt++) {
        const int k0 = kt * 64;
        __syncthreads();   // previous tile's ldmatrix reads done
        {
            const float* ksrc = g_Kh + head_base + (size_t)k0 * D_K;
            const float* vsrc = g_Vh + head_base + (size_t)k0 * D_K;
#pragma unroll
            for (int i = 0; i < 8; i++) {
                int lin = tid + i * 128;
                int r   = lin >> 4;
                int c4  = (lin & 15) * 4;
                uint32_t soff = (uint32_t)(r * HST + c4) * 2;
                float4 kv = *(const float4*)&ksrc[r * 64 + c4];
                uint32_t k0p = pack_f16x2(kv.x, kv.y);
                uint32_t k1p = pack_f16x2(kv.z, kv.w);
                asm volatile("st.shared.v2.b32 [%0], {%1,%2};"
                             :: "r"(KsB + soff), "r"(k0p), "r"(k1p));
                float4 vv = *(const float4*)&vsrc[r * 64 + c4];
                uint32_t v0p = pack_f16x2(vv.x, vv.y);
                uint32_t v1p = pack_f16x2(vv.z, vv.w);
                asm volatile("st.shared.v2.b32 [%0], {%1,%2};"
                             :: "r"(VsB + soff), "r"(v0p), "r"(v1p));
            }
            if (tid < 64) km_s[tid] = kmask[b * SEQ + k0 + tid];
        }
        __syncthreads();

        // S = Q K^T : 4 k-chunks x 4 nf-pairs, ldmatrix.x4 per pair
        float cs[8][4];
#pragma unroll
        for (int nf = 0; nf < 8; nf++)
#pragma unroll
            for (int r = 0; r < 4; r++) cs[nf][r] = 0.0f;

#pragma unroll
        for (int j = 0; j < 4; j++) {
#pragma unroll
            for (int p = 0; p < 4; p++) {
                uint32_t b0, b1, b2, b3;
                ldsm_x4(b0, b1, b2, b3,
                        KsB + offK + (uint32_t)(p * 16 * (HST * 2) + j * 32));
                mma_f16(cs[2 * p],     aq[j], b0, b1);
                mma_f16(cs[2 * p + 1], aq[j], b2, b3);
            }
        }

        // Mask + scale (causal per-element only on diagonal tile)
        const bool diag = (causal != 0) && (kt == qt);
        const int qgA = q0 + wrow + g;
        const int qgB = qgA + 8;
#pragma unroll
        for (int nf = 0; nf < 8; nf++) {
            int colb = nf * 8 + 2 * tg;
            int km0 = km_s[colb];
            int km1 = km_s[colb + 1];
            int kg0 = k0 + colb;
            int kg1 = kg0 + 1;
            float v0 = cs[nf][0] * 0.125f;
            float v1 = cs[nf][1] * 0.125f;
            float v2 = cs[nf][2] * 0.125f;
            float v3 = cs[nf][3] * 0.125f;
            if (km0 == 0 || (diag && kg0 > qgA)) v0 = -INFINITY;
            if (km1 == 0 || (diag && kg1 > qgA)) v1 = -INFINITY;
            if (km0 == 0 || (diag && kg0 > qgB)) v2 = -INFINITY;
            if (km1 == 0 || (diag && kg1 > qgB)) v3 = -INFINITY;
            cs[nf][0] = v0; cs[nf][1] = v1; cs[nf][2] = v2; cs[nf][3] = v3;
        }

        // Register online softmax (two rows per thread)
#pragma unroll
        for (int ri = 0; ri < 2; ri++) {
            float mx = -INFINITY;
#pragma unroll
            for (int nf = 0; nf < 8; nf++) {
                mx = fmaxf(mx, cs[nf][2 * ri]);
                mx = fmaxf(mx, cs[nf][2 * ri + 1]);
            }
            mx = fmaxf(mx, __shfl_xor_sync(0xffffffffu, mx, 1));
            mx = fmaxf(mx, __shfl_xor_sync(0xffffffffu, mx, 2));

            float mo = m_r[ri];
            float mn = fmaxf(mo, mx);
            float sc, sum = 0.0f;
            if (mn == -INFINITY) {
                sc = 1.0f;
#pragma unroll
                for (int nf = 0; nf < 8; nf++) {
                    cs[nf][2 * ri] = 0.0f;
                    cs[nf][2 * ri + 1] = 0.0f;
                }
            } else {
                sc = __expf(mo - mn);          // mo = -inf -> 0
#pragma unroll
                for (int nf = 0; nf < 8; nf++) {
                    float p0 = __expf(cs[nf][2 * ri] - mn);      // -inf -> 0
                    float p1 = __expf(cs[nf][2 * ri + 1] - mn);
                    cs[nf][2 * ri] = p0;
                    cs[nf][2 * ri + 1] = p1;
                    sum += p0 + p1;
                }
                m_r[ri] = mn;
            }
            sum += __shfl_xor_sync(0xffffffffu, sum, 1);
            sum += __shfl_xor_sync(0xffffffffu, sum, 2);
            l_r[ri] = l_r[ri] * sc + sum;

#pragma unroll
            for (int nf = 0; nf < 8; nf++) {
                o[nf][2 * ri]     *= sc;
                o[nf][2 * ri + 1] *= sc;
            }
        }

        // Pack P into f16 A-fragments (FA2 layout identity; no smem roundtrip)
        uint32_t pf[4][4];
#pragma unroll
        for (int j = 0; j < 4; j++) {
            pf[j][0] = pack_f16x2(cs[2 * j][0],     cs[2 * j][1]);
            pf[j][1] = pack_f16x2(cs[2 * j][2],     cs[2 * j][3]);
            pf[j][2] = pack_f16x2(cs[2 * j + 1][0], cs[2 * j + 1][1]);
            pf[j][3] = pack_f16x2(cs[2 * j + 1][2], cs[2 * j + 1][3]);
        }

        // O += P V : ldmatrix.x4.trans transposes V tiles in hardware
#pragma unroll
        for (int j = 0; j < 4; j++) {
#pragma unroll
            for (int p = 0; p < 4; p++) {
                uint32_t b0, b1, b2, b3;
                ldsm_x4_trans(b0, b1, b2, b3,
                              VsB + offV + (uint32_t)(j * 16 * (HST * 2) + p * 32));
                mma_f16(o[2 * p],     pf[j], b0, b1);
                mma_f16(o[2 * p + 1], pf[j], b2, b3);
            }
        }
    }

    // Epilogue: divide by l (0/0 -> NaN matches ref), q_mask, write [B,S,D]
#pragma unroll
    for (int ri = 0; ri < 2; ri++) {
        int r_loc = wrow + g + ri * 8;
        int qg    = q0 + r_loc;
        int qmv   = qmask[b * SEQ + qg];
        float l   = l_r[ri];
        float* dst = g_At + (size_t)(b * SEQ + qg) * D_MODEL + h * D_K;
#pragma unroll
        for (int nf = 0; nf < 8; nf++) {
            float v0 = o[nf][2 * ri]     / l;
            float v1 = o[nf][2 * ri + 1] / l;
            if (qmv == 0) { v0 = 0.0f; v1 = 0.0f; }
            float2 pr = make_float2(v0, v1);
            *(float2*)&dst[nf * 8 + 2 * tg] = pr;
        }
    }
}

// ---------------------------------------------------------------------------
extern "C" void kernel_launch(void* const* d_in, const int* in_sizes, int n_in,
                              void* d_out, int out_size)
{
    const float* q  = (const float*)d_in[0];
    const float* k  = (const float*)d_in[1];
    const int*   qm = (const int*)  d_in[2];
    const int*   km = (const int*)  d_in[3];
    const float* Wq = (const float*)d_in[4];
    const float* bq = (const float*)d_in[5];
    const float* Wk = (const float*)d_in[6];
    const float* bk = (const float*)d_in[7];
    const float* Wv = (const float*)d_in[8];
    const float* bv = (const float*)d_in[9];
    const float* Wo = (const float*)d_in[10];
    const float* bo = (const float*)d_in[11];
    const int*   cz = (const int*)  d_in[12];
    float* out = (float*)d_out;

    float *Qh, *Kh, *Vh, *At;
    cudaGetSymbolAddress((void**)&Qh, g_Qh);
    cudaGetSymbolAddress((void**)&Kh, g_Kh);
    cudaGetSymbolAddress((void**)&Vh, g_Vh);
    cudaGetSymbolAddress((void**)&At, g_At);

    // Batched Q/K/V projections (proven R10 GEMM)
    dim3 pgrid(D_MODEL / 128, M_ROWS / 128, 3);   // (8, 32, 3)
    gemm_proj3_kernel<<<pgrid, 256>>>(q, k, Wq, bq, Wk, bk, Wv, bv, Qh, Kh, Vh);

    // f16 flash attention (static smem, ~28KB)
    attn_mma_kernel<<<dim3(SEQ / 64, B_SZ * NHEAD), 128>>>(qm, km, cz);

    // Output projection
    dim3 ogrid(D_MODEL / 128, M_ROWS / 128);      // (8, 32)
    gemm_out_kernel<<<ogrid, 256>>>(At, Wo, bo, out);
}

// round 15
// speedup vs baseline: 2.4856x; 1.2616x over previous
#include <cuda_runtime.h>
#include <cuda_bf16.h>
#include <math.h>
#include <stdint.h>

// Problem constants
#define D_MODEL 1024
#define NHEAD   16
#define D_K     64
#define B_SZ    2
#define SEQ     2048
#define M_ROWS  (B_SZ * SEQ)        // 4096

// Scratch (allocation-free rule: __device__ globals)
__device__ float g_Qh[B_SZ * NHEAD * SEQ * D_K];   // [B,H,S,64]
__device__ float g_Kh[B_SZ * NHEAD * SEQ * D_K];
__device__ float g_Vh[B_SZ * NHEAD * SEQ * D_K];
__device__ float g_At[B_SZ * SEQ * D_MODEL];       // [B,S,D] merged heads

__device__ __forceinline__ uint32_t pack_f16x2(float lo, float hi) {
    uint32_t r;
    asm("cvt.rn.f16x2.f32 %0, %1, %2;" : "=r"(r) : "f"(hi), "f"(lo));  // d.lo=%2
    return r;
}

__device__ __forceinline__ void mma_f16(float c[4], const uint32_t a[4],
                                        uint32_t b0, uint32_t b1) {
    asm volatile(
        "mma.sync.aligned.m16n8k16.row.col.f32.f16.f16.f32 "
        "{%0,%1,%2,%3}, {%4,%5,%6,%7}, {%8,%9}, {%0,%1,%2,%3};"
        : "+f"(c[0]), "+f"(c[1]), "+f"(c[2]), "+f"(c[3])
        : "r"(a[0]), "r"(a[1]), "r"(a[2]), "r"(a[3]),
          "r"(b0), "r"(b1));
}

__device__ __forceinline__ void ldsm_x4(uint32_t& r0, uint32_t& r1, uint32_t& r2,
                                        uint32_t& r3, uint32_t addr) {
    asm volatile("ldmatrix.sync.aligned.m8n8.x4.shared.b16 {%0,%1,%2,%3}, [%4];"
                 : "=r"(r0), "=r"(r1), "=r"(r2), "=r"(r3) : "r"(addr));
}

__device__ __forceinline__ void ldsm_x4_trans(uint32_t& r0, uint32_t& r1, uint32_t& r2,
                                              uint32_t& r3, uint32_t addr) {
    asm volatile("ldmatrix.sync.aligned.m8n8.x4.trans.shared.b16 {%0,%1,%2,%3}, [%4];"
                 : "=r"(r0), "=r"(r1), "=r"(r2), "=r"(r3) : "r"(addr));
}

__device__ __forceinline__ uint32_t smem_u32(const void* p) {
    uint32_t a;
    asm("{ .reg .u64 t; cvta.to.shared.u64 t, %1; cvt.u32.u64 %0, t; }" : "=r"(a) : "l"(p));
    return a;
}

// ---------------------------------------------------------------------------
// f16 tensor-core GEMM body:  C[M,N] = A[M,K] @ W[N,K]^T + bias[N]
// 128x128 tile, BK=32, 256 threads = 8 warps (warp tile 64x32).
// m16n8k16 MMA; operands staged as f16, fragments via ldmatrix.x4.
// MODE 0: row-major [M,N].  MODE 1: head-split [B,H,S,64].
// ---------------------------------------------------------------------------
#define GST 40   // halves per smem row (80 B) — ldmatrix conflict-free

template <int MODE>
__device__ __forceinline__
void gemm_body(const float* __restrict__ A,
               const float* __restrict__ W,
               const float* __restrict__ bias,
               float* __restrict__ C,
               int m0, int n0)
{
    __shared__ __align__(16) uint16_t As[128 * GST];
    __shared__ __align__(16) uint16_t Ws[128 * GST];

    const int tid  = threadIdx.x;
    const int warp = tid >> 5;
    const int lane = tid & 31;
    const int g    = lane >> 2;
    const int tg   = lane & 3;

    const int wm = (warp & 1) * 64;
    const int wn = (warp >> 1) * 32;

    const uint32_t AsB = smem_u32(As);
    const uint32_t WsB = smem_u32(Ws);

    // ldmatrix per-lane offsets (bytes). Mappings validated in attn kernel.
    const int li = lane >> 3;
    const int lr = lane & 7;
    // A-frags (row-major m x k): li&1 -> m+8, li>>1 -> k+8 halves
    const uint32_t offA = (uint32_t)((lr + (li & 1) * 8) * (GST * 2) + (li >> 1) * 16);
    // B-frags from K-major W [n][k]: li>>1 -> n+8 rows, li&1 -> k+8 halves
    const uint32_t offB = (uint32_t)((lr + (li >> 1) * 8) * (GST * 2) + (li & 1) * 16);

    float c[4][4][4];
#pragma unroll
    for (int mi = 0; mi < 4; mi++)
#pragma unroll
        for (int ni = 0; ni < 4; ni++)
#pragma unroll
            for (int r = 0; r < 4; r++) c[mi][ni][r] = 0.0f;

    for (int k0 = 0; k0 < D_MODEL; k0 += 32) {
        // Stage 128x32 tiles as f16 (each thread: 4 float4 per operand)
#pragma unroll
        for (int i = 0; i < 4; i++) {
            int idx = tid + i * 256;
            int r   = idx >> 3;
            int c4  = idx & 7;
            uint32_t soff = (uint32_t)(r * GST + c4 * 4) * 2;
            float4 va = *(const float4*)&A[(size_t)(m0 + r) * D_MODEL + k0 + c4 * 4];
            uint32_t a0 = pack_f16x2(va.x, va.y);
            uint32_t a1 = pack_f16x2(va.z, va.w);
            asm volatile("st.shared.v2.b32 [%0], {%1,%2};"
                         :: "r"(AsB + soff), "r"(a0), "r"(a1));
            float4 vw = *(const float4*)&W[(size_t)(n0 + r) * D_MODEL + k0 + c4 * 4];
            uint32_t w0 = pack_f16x2(vw.x, vw.y);
            uint32_t w1 = pack_f16x2(vw.z, vw.w);
            asm volatile("st.shared.v2.b32 [%0], {%1,%2};"
                         :: "r"(WsB + soff), "r"(w0), "r"(w1));
        }
        __syncthreads();

#pragma unroll
        for (int j = 0; j < 2; j++) {        // two k16 steps per chunk
            uint32_t a[4][4];
#pragma unroll
            for (int mi = 0; mi < 4; mi++)
                ldsm_x4(a[mi][0], a[mi][1], a[mi][2], a[mi][3],
                        AsB + (uint32_t)((wm + mi * 16) * (GST * 2)) + offA
                            + (uint32_t)(j * 32));
            uint32_t b[4][2];
#pragma unroll
            for (int p = 0; p < 2; p++) {    // two n16 blocks
                uint32_t b0, b1, b2, b3;
                ldsm_x4(b0, b1, b2, b3,
                        WsB + (uint32_t)((wn + p * 16) * (GST * 2)) + offB
                            + (uint32_t)(j * 32));
                b[2 * p][0] = b0; b[2 * p][1] = b1;
                b[2 * p + 1][0] = b2; b[2 * p + 1][1] = b3;
            }
#pragma unroll
            for (int mi = 0; mi < 4; mi++)
#pragma unroll
                for (int ni = 0; ni < 4; ni++)
                    mma_f16(c[mi][ni], a[mi], b[ni][0], b[ni][1]);
        }
        __syncthreads();
    }

    // Epilogue: add bias, store (same fragment layout as before).
#pragma unroll
    for (int mi = 0; mi < 4; mi++) {
#pragma unroll
        for (int ni = 0; ni < 4; ni++) {
            int row = m0 + wm + mi * 16 + g;
            int col = n0 + wn + ni * 8 + 2 * tg;
#pragma unroll
            for (int rr = 0; rr < 2; rr++) {
                int m = row + rr * 8;
#pragma unroll
                for (int cc = 0; cc < 2; cc++) {
                    int n = col + cc;
                    float v = c[mi][ni][rr * 2 + cc] + bias[n];
                    if (MODE == 0) {
                        C[(size_t)m * D_MODEL + n] = v;
                    } else {
                        int bb = m >> 11;
                        int s  = m & 2047;
                        int h  = n >> 6;
                        int d  = n & 63;
                        C[(((size_t)(bb * NHEAD + h) * SEQ) + s) * D_K + d] = v;
                    }
                }
            }
        }
    }
}

__global__ __launch_bounds__(256, 2)
void gemm_proj3_kernel(const float* __restrict__ q,
                       const float* __restrict__ k,
                       const float* __restrict__ Wq, const float* __restrict__ bq,
                       const float* __restrict__ Wk, const float* __restrict__ bk,
                       const float* __restrict__ Wv, const float* __restrict__ bv,
                       float* __restrict__ Qh, float* __restrict__ Kh,
                       float* __restrict__ Vh)
{
    const int z = blockIdx.z;
    const float* A    = (z == 0) ? q  : k;
    const float* W    = (z == 0) ? Wq : (z == 1) ? Wk : Wv;
    const float* bias = (z == 0) ? bq : (z == 1) ? bk : bv;
    float*       C    = (z == 0) ? Qh : (z == 1) ? Kh : Vh;
    gemm_body<1>(A, W, bias, C, blockIdx.y * 128, blockIdx.x * 128);
}

__global__ __launch_bounds__(256, 2)
void gemm_out_kernel(const float* __restrict__ A,
                     const float* __restrict__ W,
                     const float* __restrict__ bias,
                     float* __restrict__ C)
{
    gemm_body<0>(A, W, bias, C, blockIdx.y * 128, blockIdx.x * 128);
}

// ---------------------------------------------------------------------------
// f16 flash attention (proven R14 version, unchanged).
// ---------------------------------------------------------------------------
#define HST 72   // halves per smem row (144 B)

__global__ __launch_bounds__(128)
void attn_mma_kernel(const int* __restrict__ qmask,
                     const int* __restrict__ kmask,
                     const int* __restrict__ causal_flag)
{
    __shared__ __align__(16) uint16_t Qs[64 * HST];
    __shared__ __align__(16) uint16_t Ks[64 * HST];
    __shared__ __align__(16) uint16_t Vs[64 * HST];
    __shared__ int km_s[64];

    const int tid  = threadIdx.x;
    const int warp = tid >> 5;
    const int lane = tid & 31;
    const int g    = lane >> 2;
    const int tg   = lane & 3;
    const int wrow = warp * 16;

    const int qt = (gridDim.x - 1) - blockIdx.x;   // longest blocks first
    const int bh = blockIdx.y;
    const int b  = bh >> 4;
    const int h  = bh & 15;
    const int q0 = qt * 64;
    const int causal = causal_flag[0];
    const size_t head_base = (size_t)bh * SEQ * D_K;

    const uint32_t QsB = smem_u32(Qs);
    const uint32_t KsB = smem_u32(Ks);
    const uint32_t VsB = smem_u32(Vs);

    const int li = lane >> 3;
    const int lr = lane & 7;
    const uint32_t offQ = (uint32_t)((lr + (li & 1) * 8) * (HST * 2) + (li >> 1) * 16);
    const uint32_t offK = (uint32_t)((lr + (li >> 1) * 8) * (HST * 2) + (li & 1) * 16);
    const uint32_t offV = (uint32_t)((lr + (li & 1) * 8) * (HST * 2) + (li >> 1) * 16);

    {
        const float* qsrc = g_Qh + head_base + (size_t)q0 * D_K;
#pragma unroll
        for (int i = 0; i < 8; i++) {
            int lin = tid + i * 128;
            int r   = lin >> 4;
            int c4  = (lin & 15) * 4;
            float4 v = *(const float4*)&qsrc[r * 64 + c4];
            uint32_t u0 = pack_f16x2(v.x, v.y);
            uint32_t u1 = pack_f16x2(v.z, v.w);
            asm volatile("st.shared.v2.b32 [%0], {%1,%2};"
                         :: "r"(QsB + (uint32_t)(r * HST + c4) * 2), "r"(u0), "r"(u1));
        }
    }
    __syncthreads();

    uint32_t aq[4][4];
#pragma unroll
    for (int j = 0; j < 4; j++)
        ldsm_x4(aq[j][0], aq[j][1], aq[j][2], aq[j][3],
                QsB + (uint32_t)(wrow * (HST * 2)) + offQ + (uint32_t)(j * 32));

    float m_r[2] = { -INFINITY, -INFINITY };
    float l_r[2] = { 0.0f, 0.0f };
    float o[8][4];
#pragma unroll
    for (int nf = 0; nf < 8; nf++)
#pragma unroll
        for (int r = 0; r < 4; r++) o[nf][r] = 0.0f;

    const int ntiles = causal ? (qt + 1) : (SEQ / 64);

    for (int kt = 0; kt < ntiles; kt++) {
        const int k0 = kt * 64;
        __syncthreads();
        {
            const float* ksrc = g_Kh + head_base + (size_t)k0 * D_K;
            const float* vsrc = g_Vh + head_base + (size_t)k0 * D_K;
#pragma unroll
            for (int i = 0; i < 8; i++) {
                int lin = tid + i * 128;
                int r   = lin >> 4;
                int c4  = (lin & 15) * 4;
                uint32_t soff = (uint32_t)(r * HST + c4) * 2;
                float4 kv = *(const float4*)&ksrc[r * 64 + c4];
                uint32_t k0p = pack_f16x2(kv.x, kv.y);
                uint32_t k1p = pack_f16x2(kv.z, kv.w);
                asm volatile("st.shared.v2.b32 [%0], {%1,%2};"
                             :: "r"(KsB + soff), "r"(k0p), "r"(k1p));
                float4 vv = *(const float4*)&vsrc[r * 64 + c4];
                uint32_t v0p = pack_f16x2(vv.x, vv.y);
                uint32_t v1p = pack_f16x2(vv.z, vv.w);
                asm volatile("st.shared.v2.b32 [%0], {%1,%2};"
                             :: "r"(VsB + soff), "r"(v0p), "r"(v1p));
            }
            if (tid < 64) km_s[tid] = kmask[b * SEQ + k0 + tid];
        }
        __syncthreads();

        float cs[8][4];
#pragma unroll
        for (int nf = 0; nf < 8; nf++)
#pragma unroll
            for (int r = 0; r < 4; r++) cs[nf][r] = 0.0f;

#pragma unroll
        for (int j = 0; j < 4; j++) {
#pragma unroll
            for (int p = 0; p < 4; p++) {
                uint32_t b0, b1, b2, b3;
                ldsm_x4(b0, b1, b2, b3,
                        KsB + offK + (uint32_t)(p * 16 * (HST * 2) + j * 32));
                mma_f16(cs[2 * p],     aq[j], b0, b1);
                mma_f16(cs[2 * p + 1], aq[j], b2, b3);
            }
        }

        const bool diag = (causal != 0) && (kt == qt);
        const int qgA = q0 + wrow + g;
        const int qgB = qgA + 8;
#pragma unroll
        for (int nf = 0; nf < 8; nf++) {
            int colb = nf * 8 + 2 * tg;
            int km0 = km_s[colb];
            int km1 = km_s[colb + 1];
            int kg0 = k0 + colb;
            int kg1 = kg0 + 1;
            float v0 = cs[nf][0] * 0.125f;
            float v1 = cs[nf][1] * 0.125f;
            float v2 = cs[nf][2] * 0.125f;
            float v3 = cs[nf][3] * 0.125f;
            if (km0 == 0 || (diag && kg0 > qgA)) v0 = -INFINITY;
            if (km1 == 0 || (diag && kg1 > qgA)) v1 = -INFINITY;
            if (km0 == 0 || (diag && kg0 > qgB)) v2 = -INFINITY;
            if (km1 == 0 || (diag && kg1 > qgB)) v3 = -INFINITY;
            cs[nf][0] = v0; cs[nf][1] = v1; cs[nf][2] = v2; cs[nf][3] = v3;
        }

#pragma unroll
        for (int ri = 0; ri < 2; ri++) {
            float mx = -INFINITY;
#pragma unroll
            for (int nf = 0; nf < 8; nf++) {
                mx = fmaxf(mx, cs[nf][2 * ri]);
                mx = fmaxf(mx, cs[nf][2 * ri + 1]);
            }
            mx = fmaxf(mx, __shfl_xor_sync(0xffffffffu, mx, 1));
            mx = fmaxf(mx, __shfl_xor_sync(0xffffffffu, mx, 2));

            float mo = m_r[ri];
            float mn = fmaxf(mo, mx);
            float sc, sum = 0.0f;
            if (mn == -INFINITY) {
                sc = 1.0f;
#pragma unroll
                for (int nf = 0; nf < 8; nf++) {
                    cs[nf][2 * ri] = 0.0f;
                    cs[nf][2 * ri + 1] = 0.0f;
                }
            } else {
                sc = __expf(mo - mn);          // mo = -inf -> 0
#pragma unroll
                for (int nf = 0; nf < 8; nf++) {
                    float p0 = __expf(cs[nf][2 * ri] - mn);      // -inf -> 0
                    float p1 = __expf(cs[nf][2 * ri + 1] - mn);
                    cs[nf][2 * ri] = p0;
                    cs[nf][2 * ri + 1] = p1;
                    sum += p0 + p1;
                }
                m_r[ri] = mn;
            }
            sum += __shfl_xor_sync(0xffffffffu, sum, 1);
            sum += __shfl_xor_sync(0xffffffffu, sum, 2);
            l_r[ri] = l_r[ri] * sc + sum;

#pragma unroll
            for (int nf = 0; nf < 8; nf++) {
                o[nf][2 * ri]     *= sc;
                o[nf][2 * ri + 1] *= sc;
            }
        }

        uint32_t pf[4][4];
#pragma unroll
        for (int j = 0; j < 4; j++) {
            pf[j][0] = pack_f16x2(cs[2 * j][0],     cs[2 * j][1]);
            pf[j][1] = pack_f16x2(cs[2 * j][2],     cs[2 * j][3]);
            pf[j][2] = pack_f16x2(cs[2 * j + 1][0], cs[2 * j + 1][1]);
            pf[j][3] = pack_f16x2(cs[2 * j + 1][2], cs[2 * j + 1][3]);
        }

#pragma unroll
        for (int j = 0; j < 4; j++) {
#pragma unroll
            for (int p = 0; p < 4; p++) {
                uint32_t b0, b1, b2, b3;
                ldsm_x4_trans(b0, b1, b2, b3,
                              VsB + offV + (uint32_t)(j * 16 * (HST * 2) + p * 32));
                mma_f16(o[2 * p],     pf[j], b0, b1);
                mma_f16(o[2 * p + 1], pf[j], b2, b3);
            }
        }
    }

#pragma unroll
    for (int ri = 0; ri < 2; ri++) {
        int r_loc = wrow + g + ri * 8;
        int qg    = q0 + r_loc;
        int qmv   = qmask[b * SEQ + qg];
        float l   = l_r[ri];
        float* dst = g_At + (size_t)(b * SEQ + qg) * D_MODEL + h * D_K;
#pragma unroll
        for (int nf = 0; nf < 8; nf++) {
            float v0 = o[nf][2 * ri]     / l;
            float v1 = o[nf][2 * ri + 1] / l;
            if (qmv == 0) { v0 = 0.0f; v1 = 0.0f; }
            float2 pr = make_float2(v0, v1);
            *(float2*)&dst[nf * 8 + 2 * tg] = pr;
        }
    }
}

// ---------------------------------------------------------------------------
extern "C" void kernel_launch(void* const* d_in, const int* in_sizes, int n_in,
                              void* d_out, int out_size)
{
    const float* q  = (const float*)d_in[0];
    const float* k  = (const float*)d_in[1];
    const int*   qm = (const int*)  d_in[2];
    const int*   km = (const int*)  d_in[3];
    const float* Wq = (const float*)d_in[4];
    const float* bq = (const float*)d_in[5];
    const float* Wk = (const float*)d_in[6];
    const float* bk = (const float*)d_in[7];
    const float* Wv = (const float*)d_in[8];
    const float* bv = (const float*)d_in[9];
    const float* Wo = (const float*)d_in[10];
    const float* bo = (const float*)d_in[11];
    const int*   cz = (const int*)  d_in[12];
    float* out = (float*)d_out;

    float *Qh, *Kh, *Vh, *At;
    cudaGetSymbolAddress((void**)&Qh, g_Qh);
    cudaGetSymbolAddress((void**)&Kh, g_Kh);
    cudaGetSymbolAddress((void**)&Vh, g_Vh);
    cudaGetSymbolAddress((void**)&At, g_At);

    // Batched Q/K/V projections (f16 tensor-core)
    dim3 pgrid(D_MODEL / 128, M_ROWS / 128, 3);   // (8, 32, 3)
    gemm_proj3_kernel<<<pgrid, 256>>>(q, k, Wq, bq, Wk, bk, Wv, bv, Qh, Kh, Vh);

    // f16 flash attention
    attn_mma_kernel<<<dim3(SEQ / 64, B_SZ * NHEAD), 128>>>(qm, km, cz);

    // Output projection (f16 tensor-core)
    dim3 ogrid(D_MODEL / 128, M_ROWS / 128);      // (8, 32)
    gemm_out_kernel<<<ogrid, 256>>>(At, Wo, bo, out);
}

// round 16
// speedup vs baseline: 3.2240x; 1.2971x over previous
#include <cuda_runtime.h>
#include <cuda_bf16.h>
#include <math.h>
#include <stdint.h>

// Problem constants
#define D_MODEL 1024
#define NHEAD   16
#define D_K     64
#define B_SZ    2
#define SEQ     2048
#define M_ROWS  (B_SZ * SEQ)        // 4096

// f16 scratch (allocation-free rule: __device__ globals)
__device__ uint16_t g_qf [M_ROWS * D_MODEL];           // q  in f16
__device__ uint16_t g_kf [M_ROWS * D_MODEL];           // k  in f16
__device__ uint16_t g_Wqf[D_MODEL * D_MODEL];
__device__ uint16_t g_Wkf[D_MODEL * D_MODEL];
__device__ uint16_t g_Wvf[D_MODEL * D_MODEL];
__device__ uint16_t g_Wof[D_MODEL * D_MODEL];
__device__ uint16_t g_Qh [B_SZ * NHEAD * SEQ * D_K];   // [B,H,S,64] f16
__device__ uint16_t g_Kh [B_SZ * NHEAD * SEQ * D_K];
__device__ uint16_t g_Vh [B_SZ * NHEAD * SEQ * D_K];
__device__ uint16_t g_At [B_SZ * SEQ * D_MODEL];       // [B,S,D] f16

__device__ __forceinline__ uint32_t pack_f16x2(float lo, float hi) {
    uint32_t r;
    asm("cvt.rn.f16x2.f32 %0, %1, %2;" : "=r"(r) : "f"(hi), "f"(lo));  // d.lo=%2
    return r;
}

__device__ __forceinline__ void mma_f16(float c[4], const uint32_t a[4],
                                        uint32_t b0, uint32_t b1) {
    asm volatile(
        "mma.sync.aligned.m16n8k16.row.col.f32.f16.f16.f32 "
        "{%0,%1,%2,%3}, {%4,%5,%6,%7}, {%8,%9}, {%0,%1,%2,%3};"
        : "+f"(c[0]), "+f"(c[1]), "+f"(c[2]), "+f"(c[3])
        : "r"(a[0]), "r"(a[1]), "r"(a[2]), "r"(a[3]),
          "r"(b0), "r"(b1));
}

__device__ __forceinline__ void ldsm_x4(uint32_t& r0, uint32_t& r1, uint32_t& r2,
                                        uint32_t& r3, uint32_t addr) {
    asm volatile("ldmatrix.sync.aligned.m8n8.x4.shared.b16 {%0,%1,%2,%3}, [%4];"
                 : "=r"(r0), "=r"(r1), "=r"(r2), "=r"(r3) : "r"(addr));
}

__device__ __forceinline__ void ldsm_x4_trans(uint32_t& r0, uint32_t& r1, uint32_t& r2,
                                              uint32_t& r3, uint32_t addr) {
    asm volatile("ldmatrix.sync.aligned.m8n8.x4.trans.shared.b16 {%0,%1,%2,%3}, [%4];"
                 : "=r"(r0), "=r"(r1), "=r"(r2), "=r"(r3) : "r"(addr));
}

__device__ __forceinline__ uint32_t smem_u32(const void* p) {
    uint32_t a;
    asm("{ .reg .u64 t; cvta.to.shared.u64 t, %1; cvt.u32.u64 %0, t; }" : "=r"(a) : "l"(p));
    return a;
}

#define CP_ASYNC16(dst_u32, src_ptr) \
    asm volatile("cp.async.ca.shared.global [%0], [%1], 16;" \
                 :: "r"(dst_u32), "l"(src_ptr) : "memory")
#define CP_COMMIT() asm volatile("cp.async.commit_group;" ::: "memory")
#define CP_WAIT0()  asm volatile("cp.async.wait_group 0;" ::: "memory")

// ---------------------------------------------------------------------------
// fp32 -> f16 conversion pre-pass. blockIdx.y selects tensor.
// ---------------------------------------------------------------------------
__global__ void cvt_f16_kernel(const float* s0, const float* s1, const float* s2,
                               const float* s3, const float* s4, const float* s5,
                               uint16_t* d0, uint16_t* d1, uint16_t* d2,
                               uint16_t* d3, uint16_t* d4, uint16_t* d5)
{
    const int t = blockIdx.y;
    const float* s = (t == 0) ? s0 : (t == 1) ? s1 : (t == 2) ? s2
                   : (t == 3) ? s3 : (t == 4) ? s4 : s5;
    uint16_t* d    = (t == 0) ? d0 : (t == 1) ? d1 : (t == 2) ? d2
                   : (t == 3) ? d3 : (t == 4) ? d4 : d5;
    const int quads = ((t < 2) ? (M_ROWS * D_MODEL) : (D_MODEL * D_MODEL)) >> 2;
    for (int i = blockIdx.x * blockDim.x + threadIdx.x; i < quads;
         i += gridDim.x * blockDim.x) {
        float4 v = ((const float4*)s)[i];
        uint2 p;
        p.x = pack_f16x2(v.x, v.y);
        p.y = pack_f16x2(v.z, v.w);
        ((uint2*)d)[i] = p;
    }
}

// ---------------------------------------------------------------------------
// cp.async-pipelined f16 GEMM:  C[M,N] = A[M,K] @ W[N,K]^T + bias[N]
// A, W already f16. 128x128 tile, BK=32, 256 threads (8 warps, 64x32 each).
// Double-buffered smem; chunk ch+1 streams in while chunk ch computes.
// MODE 0: fp32 row-major [M,N].  MODE 1: f16 head-split [B,H,S,64].
// ---------------------------------------------------------------------------
#define GST 40   // halves per smem row (80 B) — ldmatrix conflict-free

template <int MODE>
__device__ __forceinline__
void gemm_body(const uint16_t* __restrict__ A,
               const uint16_t* __restrict__ W,
               const float* __restrict__ bias,
               void* __restrict__ Cv,
               int m0, int n0)
{
    __shared__ __align__(16) uint16_t sb[4][128 * GST];  // A0, W0, A1, W1

    const int tid  = threadIdx.x;
    const int warp = tid >> 5;
    const int lane = tid & 31;
    const int g    = lane >> 2;
    const int tg   = lane & 3;

    const int wm = (warp & 1) * 64;
    const int wn = (warp >> 1) * 32;

    const uint32_t sA0 = smem_u32(sb[0]);
    const uint32_t sW0 = smem_u32(sb[1]);
    const uint32_t sA1 = smem_u32(sb[2]);
    const uint32_t sW1 = smem_u32(sb[3]);

    const int li = lane >> 3;
    const int lr = lane & 7;
    const uint32_t offA = (uint32_t)((lr + (li & 1) * 8) * (GST * 2) + (li >> 1) * 16);
    const uint32_t offB = (uint32_t)((lr + (li >> 1) * 8) * (GST * 2) + (li & 1) * 16);

    // staging coords: thread covers rows r0 and r0+64, 16B col block c16
    const int r0  = tid >> 2;
    const int c16 = tid & 3;
    const uint16_t* Asrc = A + (size_t)(m0 + r0) * D_MODEL + c16 * 8;
    const uint16_t* Wsrc = W + (size_t)(n0 + r0) * D_MODEL + c16 * 8;
    const uint32_t stoff = (uint32_t)(r0 * GST + c16 * 8) * 2;
    const uint32_t rowB  = 64 * GST * 2;   // +64 rows in bytes
    const size_t  srow64 = (size_t)64 * D_MODEL;

    float c[4][4][4];
#pragma unroll
    for (int mi = 0; mi < 4; mi++)
#pragma unroll
        for (int ni = 0; ni < 4; ni++)
#pragma unroll
            for (int r = 0; r < 4; r++) c[mi][ni][r] = 0.0f;

    // prologue: chunk 0 -> buf0
    CP_ASYNC16(sA0 + stoff, Asrc);
    CP_ASYNC16(sA0 + stoff + rowB, Asrc + srow64);
    CP_ASYNC16(sW0 + stoff, Wsrc);
    CP_ASYNC16(sW0 + stoff + rowB, Wsrc + srow64);
    CP_COMMIT();

    for (int ch = 0; ch < D_MODEL / 32; ch++) {
        CP_WAIT0();
        __syncthreads();     // chunk ch visible to all; compute(ch-1) done by all

        if (ch + 1 < D_MODEL / 32) {
            const int k1 = (ch + 1) * 32;
            const uint32_t dA = ((ch + 1) & 1) ? sA1 : sA0;
            const uint32_t dW = ((ch + 1) & 1) ? sW1 : sW0;
            CP_ASYNC16(dA + stoff, Asrc + k1);
            CP_ASYNC16(dA + stoff + rowB, Asrc + srow64 + k1);
            CP_ASYNC16(dW + stoff, Wsrc + k1);
            CP_ASYNC16(dW + stoff + rowB, Wsrc + srow64 + k1);
            CP_COMMIT();
        }

        const uint32_t AsB = (ch & 1) ? sA1 : sA0;
        const uint32_t WsB = (ch & 1) ? sW1 : sW0;

#pragma unroll
        for (int j = 0; j < 2; j++) {        // two k16 steps per chunk
            uint32_t a[4][4];
#pragma unroll
            for (int mi = 0; mi < 4; mi++)
                ldsm_x4(a[mi][0], a[mi][1], a[mi][2], a[mi][3],
                        AsB + (uint32_t)((wm + mi * 16) * (GST * 2)) + offA
                            + (uint32_t)(j * 32));
            uint32_t b[4][2];
#pragma unroll
            for (int p = 0; p < 2; p++) {
                uint32_t b0, b1, b2, b3;
                ldsm_x4(b0, b1, b2, b3,
                        WsB + (uint32_t)((wn + p * 16) * (GST * 2)) + offB
                            + (uint32_t)(j * 32));
                b[2 * p][0] = b0; b[2 * p][1] = b1;
                b[2 * p + 1][0] = b2; b[2 * p + 1][1] = b3;
            }
#pragma unroll
            for (int mi = 0; mi < 4; mi++)
#pragma unroll
                for (int ni = 0; ni < 4; ni++)
                    mma_f16(c[mi][ni], a[mi], b[ni][0], b[ni][1]);
        }
        // no trailing sync: next iter's sync (post-wait) orders buffer reuse
    }

    // Epilogue: add bias, store.
#pragma unroll
    for (int mi = 0; mi < 4; mi++) {
#pragma unroll
        for (int ni = 0; ni < 4; ni++) {
            int row = m0 + wm + mi * 16 + g;
            int col = n0 + wn + ni * 8 + 2 * tg;
            float b0 = bias[col], b1 = bias[col + 1];
#pragma unroll
            for (int rr = 0; rr < 2; rr++) {
                int m = row + rr * 8;
                float v0 = c[mi][ni][rr * 2]     + b0;
                float v1 = c[mi][ni][rr * 2 + 1] + b1;
                if (MODE == 0) {
                    float2 pr = make_float2(v0, v1);
                    *(float2*)&((float*)Cv)[(size_t)m * D_MODEL + col] = pr;
                } else {
                    int bb = m >> 11;
                    int s  = m & 2047;
                    int h  = col >> 6;
                    int d  = col & 63;
                    uint16_t* dst = (uint16_t*)Cv
                        + (((size_t)(bb * NHEAD + h) * SEQ) + s) * D_K + d;
                    *(uint32_t*)dst = pack_f16x2(v0, v1);
                }
            }
        }
    }
}

__global__ __launch_bounds__(256, 2)
void gemm_proj3_kernel(const uint16_t* __restrict__ qf,
                       const uint16_t* __restrict__ kf,
                       const float* __restrict__ bq,
                       const float* __restrict__ bk,
                       const float* __restrict__ bv,
                       uint16_t* __restrict__ Qh, uint16_t* __restrict__ Kh,
                       uint16_t* __restrict__ Vh)
{
    const int z = blockIdx.z;
    const uint16_t* A = (z == 0) ? qf : kf;
    const uint16_t* W = (z == 0) ? g_Wqf : (z == 1) ? g_Wkf : g_Wvf;
    const float* bias = (z == 0) ? bq : (z == 1) ? bk : bv;
    uint16_t*    C    = (z == 0) ? Qh : (z == 1) ? Kh : Vh;
    gemm_body<1>(A, W, bias, C, blockIdx.y * 128, blockIdx.x * 128);
}

__global__ __launch_bounds__(256, 2)
void gemm_out_kernel(const uint16_t* __restrict__ A,
                     const float* __restrict__ bias,
                     float* __restrict__ C)
{
    gemm_body<0>(A, g_Wof, bias, C, blockIdx.y * 128, blockIdx.x * 128);
}

// ---------------------------------------------------------------------------
// f16 flash attention (R14/R15-proven math; staging now raw f16 copies).
// ---------------------------------------------------------------------------
#define HST 72   // halves per smem row (144 B)

__global__ __launch_bounds__(128)
void attn_mma_kernel(const int* __restrict__ qmask,
                     const int* __restrict__ kmask,
                     const int* __restrict__ causal_flag)
{
    __shared__ __align__(16) uint16_t Qs[64 * HST];
    __shared__ __align__(16) uint16_t Ks[64 * HST];
    __shared__ __align__(16) uint16_t Vs[64 * HST];
    __shared__ int km_s[64];

    const int tid  = threadIdx.x;
    const int warp = tid >> 5;
    const int lane = tid & 31;
    const int g    = lane >> 2;
    const int tg   = lane & 3;
    const int wrow = warp * 16;

    const int qt = (gridDim.x - 1) - blockIdx.x;   // longest blocks first
    const int bh = blockIdx.y;
    const int b  = bh >> 4;
    const int h  = bh & 15;
    const int q0 = qt * 64;
    const int causal = causal_flag[0];
    const size_t head_base = (size_t)bh * SEQ * D_K;

    const uint32_t QsB = smem_u32(Qs);
    const uint32_t KsB = smem_u32(Ks);
    const uint32_t VsB = smem_u32(Vs);

    const int li = lane >> 3;
    const int lr = lane & 7;
    const uint32_t offQ = (uint32_t)((lr + (li & 1) * 8) * (HST * 2) + (li >> 1) * 16);
    const uint32_t offK = (uint32_t)((lr + (li >> 1) * 8) * (HST * 2) + (li & 1) * 16);
    const uint32_t offV = (uint32_t)((lr + (li & 1) * 8) * (HST * 2) + (li >> 1) * 16);

    // Stage Q tile (raw f16 copy, 16B per thread-iter)
    {
        const uint16_t* qsrc = g_Qh + head_base + (size_t)q0 * D_K;
#pragma unroll
        for (int i = 0; i < 4; i++) {
            int lin = tid + i * 128;
            int r   = lin >> 3;
            int c8  = (lin & 7) * 8;
            uint4 v = *(const uint4*)&qsrc[r * 64 + c8];
            asm volatile("st.shared.v4.b32 [%0], {%1,%2,%3,%4};"
                         :: "r"(QsB + (uint32_t)(r * HST + c8) * 2),
                            "r"(v.x), "r"(v.y), "r"(v.z), "r"(v.w));
        }
    }
    __syncthreads();

    uint32_t aq[4][4];
#pragma unroll
    for (int j = 0; j < 4; j++)
        ldsm_x4(aq[j][0], aq[j][1], aq[j][2], aq[j][3],
                QsB + (uint32_t)(wrow * (HST * 2)) + offQ + (uint32_t)(j * 32));

    float m_r[2] = { -INFINITY, -INFINITY };
    float l_r[2] = { 0.0f, 0.0f };
    float o[8][4];
#pragma unroll
    for (int nf = 0; nf < 8; nf++)
#pragma unroll
        for (int r = 0; r < 4; r++) o[nf][r] = 0.0f;

    const int ntiles = causal ? (qt + 1) : (SEQ / 64);

    for (int kt = 0; kt < ntiles; kt++) {
        const int k0 = kt * 64;
        __syncthreads();
        {
            const uint16_t* ksrc = g_Kh + head_base + (size_t)k0 * D_K;
            const uint16_t* vsrc = g_Vh + head_base + (size_t)k0 * D_K;
#pragma unroll
            for (int i = 0; i < 4; i++) {
                int lin = tid + i * 128;
                int r   = lin >> 3;
                int c8  = (lin & 7) * 8;
                uint32_t soff = (uint32_t)(r * HST + c8) * 2;
                uint4 kv = *(const uint4*)&ksrc[r * 64 + c8];
                asm volatile("st.shared.v4.b32 [%0], {%1,%2,%3,%4};"
                             :: "r"(KsB + soff), "r"(kv.x), "r"(kv.y), "r"(kv.z), "r"(kv.w));
                uint4 vv = *(const uint4*)&vsrc[r * 64 + c8];
                asm volatile("st.shared.v4.b32 [%0], {%1,%2,%3,%4};"
                             :: "r"(VsB + soff), "r"(vv.x), "r"(vv.y), "r"(vv.z), "r"(vv.w));
            }
            if (tid < 64) km_s[tid] = kmask[b * SEQ + k0 + tid];
        }
        __syncthreads();

        float cs[8][4];
#pragma unroll
        for (int nf = 0; nf < 8; nf++)
#pragma unroll
            for (int r = 0; r < 4; r++) cs[nf][r] = 0.0f;

#pragma unroll
        for (int j = 0; j < 4; j++) {
#pragma unroll
            for (int p = 0; p < 4; p++) {
                uint32_t b0, b1, b2, b3;
                ldsm_x4(b0, b1, b2, b3,
                        KsB + offK + (uint32_t)(p * 16 * (HST * 2) + j * 32));
                mma_f16(cs[2 * p],     aq[j], b0, b1);
                mma_f16(cs[2 * p + 1], aq[j], b2, b3);
            }
        }

        const bool diag = (causal != 0) && (kt == qt);
        const int qgA = q0 + wrow + g;
        const int qgB = qgA + 8;
#pragma unroll
        for (int nf = 0; nf < 8; nf++) {
            int colb = nf * 8 + 2 * tg;
            int km0 = km_s[colb];
            int km1 = km_s[colb + 1];
            int kg0 = k0 + colb;
            int kg1 = kg0 + 1;
            float v0 = cs[nf][0] * 0.125f;
            float v1 = cs[nf][1] * 0.125f;
            float v2 = cs[nf][2] * 0.125f;
            float v3 = cs[nf][3] * 0.125f;
            if (km0 == 0 || (diag && kg0 > qgA)) v0 = -INFINITY;
            if (km1 == 0 || (diag && kg1 > qgA)) v1 = -INFINITY;
            if (km0 == 0 || (diag && kg0 > qgB)) v2 = -INFINITY;
            if (km1 == 0 || (diag && kg1 > qgB)) v3 = -INFINITY;
            cs[nf][0] = v0; cs[nf][1] = v1; cs[nf][2] = v2; cs[nf][3] = v3;
        }

#pragma unroll
        for (int ri = 0; ri < 2; ri++) {
            float mx = -INFINITY;
#pragma unroll
            for (int nf = 0; nf < 8; nf++) {
                mx = fmaxf(mx, cs[nf][2 * ri]);
                mx = fmaxf(mx, cs[nf][2 * ri + 1]);
            }
            mx = fmaxf(mx, __shfl_xor_sync(0xffffffffu, mx, 1));
            mx = fmaxf(mx, __shfl_xor_sync(0xffffffffu, mx, 2));

            float mo = m_r[ri];
            float mn = fmaxf(mo, mx);
            float sc, sum = 0.0f;
            if (mn == -INFINITY) {
                sc = 1.0f;
#pragma unroll
                for (int nf = 0; nf < 8; nf++) {
                    cs[nf][2 * ri] = 0.0f;
                    cs[nf][2 * ri + 1] = 0.0f;
                }
            } else {
                sc = __expf(mo - mn);          // mo = -inf -> 0
#pragma unroll
                for (int nf = 0; nf < 8; nf++) {
                    float p0 = __expf(cs[nf][2 * ri] - mn);      // -inf -> 0
                    float p1 = __expf(cs[nf][2 * ri + 1] - mn);
                    cs[nf][2 * ri] = p0;
                    cs[nf][2 * ri + 1] = p1;
                    sum += p0 + p1;
                }
                m_r[ri] = mn;
            }
            sum += __shfl_xor_sync(0xffffffffu, sum, 1);
            sum += __shfl_xor_sync(0xffffffffu, sum, 2);
            l_r[ri] = l_r[ri] * sc + sum;

#pragma unroll
            for (int nf = 0; nf < 8; nf++) {
                o[nf][2 * ri]     *= sc;
                o[nf][2 * ri + 1] *= sc;
            }
        }

        uint32_t pf[4][4];
#pragma unroll
        for (int j = 0; j < 4; j++) {
            pf[j][0] = pack_f16x2(cs[2 * j][0],     cs[2 * j][1]);
            pf[j][1] = pack_f16x2(cs[2 * j][2],     cs[2 * j][3]);
            pf[j][2] = pack_f16x2(cs[2 * j + 1][0], cs[2 * j + 1][1]);
            pf[j][3] = pack_f16x2(cs[2 * j + 1][2], cs[2 * j + 1][3]);
        }

#pragma unroll
        for (int j = 0; j < 4; j++) {
#pragma unroll
            for (int p = 0; p < 4; p++) {
                uint32_t b0, b1, b2, b3;
                ldsm_x4_trans(b0, b1, b2, b3,
                              VsB + offV + (uint32_t)(j * 16 * (HST * 2) + p * 32));
                mma_f16(o[2 * p],     pf[j], b0, b1);
                mma_f16(o[2 * p + 1], pf[j], b2, b3);
            }
        }
    }

    // Epilogue: divide by l (0/0 -> NaN matches ref), q_mask, write f16 [B,S,D]
#pragma unroll
    for (int ri = 0; ri < 2; ri++) {
        int r_loc = wrow + g + ri * 8;
        int qg    = q0 + r_loc;
        int qmv   = qmask[b * SEQ + qg];
        float l   = l_r[ri];
        uint16_t* dst = g_At + (size_t)(b * SEQ + qg) * D_MODEL + h * D_K;
#pragma unroll
        for (int nf = 0; nf < 8; nf++) {
            float v0 = o[nf][2 * ri]     / l;
            float v1 = o[nf][2 * ri + 1] / l;
            if (qmv == 0) { v0 = 0.0f; v1 = 0.0f; }
            *(uint32_t*)&dst[nf * 8 + 2 * tg] = pack_f16x2(v0, v1);
        }
    }
}

// ---------------------------------------------------------------------------
extern "C" void kernel_launch(void* const* d_in, const int* in_sizes, int n_in,
                              void* d_out, int out_size)
{
    const float* q  = (const float*)d_in[0];
    const float* k  = (const float*)d_in[1];
    const int*   qm = (const int*)  d_in[2];
    const int*   km = (const int*)  d_in[3];
    const float* bq = (const float*)d_in[5];
    const float* bk = (const float*)d_in[7];
    const float* bv = (const float*)d_in[9];
    const float* bo = (const float*)d_in[11];
    const float* Wq = (const float*)d_in[4];
    const float* Wk = (const float*)d_in[6];
    const float* Wv = (const float*)d_in[8];
    const float* Wo = (const float*)d_in[10];
    const int*   cz = (const int*)  d_in[12];
    float* out = (float*)d_out;

    uint16_t *qf, *kf, *Wqf, *Wkf, *Wvf, *Wof, *Qh, *Kh, *Vh, *At;
    cudaGetSymbolAddress((void**)&qf,  g_qf);
    cudaGetSymbolAddress((void**)&kf,  g_kf);
    cudaGetSymbolAddress((void**)&Wqf, g_Wqf);
    cudaGetSymbolAddress((void**)&Wkf, g_Wkf);
    cudaGetSymbolAddress((void**)&Wvf, g_Wvf);
    cudaGetSymbolAddress((void**)&Wof, g_Wof);
    cudaGetSymbolAddress((void**)&Qh,  g_Qh);
    cudaGetSymbolAddress((void**)&Kh,  g_Kh);
    cudaGetSymbolAddress((void**)&Vh,  g_Vh);
    cudaGetSymbolAddress((void**)&At,  g_At);

    // 0) fp32 -> f16 conversion pre-pass
    cvt_f16_kernel<<<dim3(512, 6), 256>>>(q, k, Wq, Wk, Wv, Wo,
                                          qf, kf, Wqf, Wkf, Wvf, Wof);

    // 1) Batched Q/K/V projections (f16, cp.async-pipelined)
    dim3 pgrid(D_MODEL / 128, M_ROWS / 128, 3);   // (8, 32, 3)
    gemm_proj3_kernel<<<pgrid, 256>>>(qf, kf, bq, bk, bv, Qh, Kh, Vh);

    // 2) f16 flash attention
    attn_mma_kernel<<<dim3(SEQ / 64, B_SZ * NHEAD), 128>>>(qm, km, cz);

    // 3) Output projection (f16, cp.async-pipelined)
    dim3 ogrid(D_MODEL / 128, M_ROWS / 128);      // (8, 32)
    gemm_out_kernel<<<ogrid, 256>>>(At, bo, out);
}